// round 14
// baseline (speedup 1.0000x reference)
#include <cuda_runtime.h>
#include <cuda_fp16.h>
#include <cstdint>

// ---------------------------------------------------------------------------
// bs=4 seg=512 nv=8 h=8 dq=32 din=256; tokens=16384, groups=256
// ALL-FP16 datapath. R14: GEMMs restructured for occupancy -- 16x64 warp
// tiles (acc=32 regs), launch_bounds(256,4) -> 32 warps/SM (was 16).
//  prep  : Wq, fc -> fp16 planes
//  gemm0 : q = (x@WqT + b)*log2e/temp; 32x256 tile, fp32 x reg-prefetch
//  attn  : 4 CTAs/group (128 rows, 128 thr, occ5); z cvt during staging
//  gemm1 : fc + bias + residual + fused LN; 32x256 tile
// ---------------------------------------------------------------------------

#define NTOK 16384
#define SEG  512
#define DQ   32
#define NG   256
#define SCALE 0.2550353055731662f   // log2(e)/sqrt(32)

typedef __half f16;

__device__ f16 g_qh[NG * SEG * DQ];
__device__ f16 g_oh[NTOK * 256];
__device__ f16 g_wqh[256 * 256];
__device__ f16 g_fh[256 * 256];

// ---------------- helpers ----------------
__device__ __forceinline__ uint32_t sptr(const void* p) {
    return (uint32_t)__cvta_generic_to_shared(p);
}
__device__ __forceinline__ void ldsm4(uint32_t& r0, uint32_t& r1, uint32_t& r2,
                                      uint32_t& r3, uint32_t a) {
    asm volatile("ldmatrix.sync.aligned.m8n8.x4.shared.b16 {%0,%1,%2,%3}, [%4];"
                 : "=r"(r0), "=r"(r1), "=r"(r2), "=r"(r3) : "r"(a));
}
__device__ __forceinline__ void ldsm4t(uint32_t& r0, uint32_t& r1, uint32_t& r2,
                                       uint32_t& r3, uint32_t a) {
    asm volatile("ldmatrix.sync.aligned.m8n8.x4.trans.shared.b16 {%0,%1,%2,%3}, [%4];"
                 : "=r"(r0), "=r"(r1), "=r"(r2), "=r"(r3) : "r"(a));
}
__device__ __forceinline__ void mma16816(float* d, const uint32_t* a,
                                         uint32_t b0, uint32_t b1) {
    asm volatile(
        "mma.sync.aligned.m16n8k16.row.col.f32.f16.f16.f32 "
        "{%0,%1,%2,%3}, {%4,%5,%6,%7}, {%8,%9}, {%0,%1,%2,%3};"
        : "+f"(d[0]), "+f"(d[1]), "+f"(d[2]), "+f"(d[3])
        : "r"(a[0]), "r"(a[1]), "r"(a[2]), "r"(a[3]), "r"(b0), "r"(b1));
}
__device__ __forceinline__ uint32_t pack_f16(float x, float y) {
    __half2 h = __floats2half2_rn(x, y);
    return *(uint32_t*)&h;
}
__device__ __forceinline__ uint32_t ex2_f16x2(uint32_t a) {
    uint32_t r;
    asm("ex2.approx.f16x2 %0, %1;" : "=r"(r) : "r"(a));
    return r;
}
__device__ __forceinline__ void cpasync16(uint32_t dst, const void* src) {
    asm volatile("cp.async.ca.shared.global [%0], [%1], 16;" :: "r"(dst), "l"(src));
}

// ---------------- prep: weights fp32 -> fp16 ----------------
__global__ __launch_bounds__(256) void prep(const float* __restrict__ wq,
                                            const float* __restrict__ fcw) {
    int blk = blockIdx.x;
    const float* src = (blk < 64) ? wq : fcw;
    f16* dh = (blk < 64) ? g_wqh : g_fh;
    int i = ((blk < 64) ? blk : blk - 64) * 256 + threadIdx.x;
    float4 v = ((const float4*)src)[i];
    ((uint2*)dh)[i] = make_uint2(pack_f16(v.x, v.y), pack_f16(v.z, v.w));
}

// ---------------------------------------------------------------------------
// gemm0: q-projection, fused x conversion. Tile 32 rows x 256 cols, 256 thr
// (8 warps: 2 row x 4 col, warp tile 16x64), BK=32, 2-stage, 4 CTAs/SM.
// ---------------------------------------------------------------------------
#define G0_A (32 * 40)
#define G0_W (256 * 40)
#define G0_SMEM ((2 * G0_A + 2 * G0_W) * 2)   // 46080

__global__ __launch_bounds__(256, 4) void gemm0(
    const float* __restrict__ Xf, const f16* __restrict__ Wh_g,
    const float* __restrict__ bias)
{
    extern __shared__ char smem_raw[];
    f16* Ahp = (f16*)smem_raw;          // [2][32][40]
    f16* Whp = Ahp + 2 * G0_A;          // [2][256][40]

    const int rb = blockIdx.x * 32;
    const int tid = threadIdx.x, lane = tid & 31, w = tid >> 5;
    const int wmi = w & 1, wn = w >> 1;   // 2 (row) x 4 (col)

    const int a_row = tid >> 3, a_j = tid & 7;   // 256 float4 chunks, 1/thread

    auto issueW = [&](int kt, int buf) {
#pragma unroll
        for (int u = 0; u < 4; u++) {
            int idx = tid + u * 256;
            int row = idx >> 2, q = (idx & 3) * 8;
            cpasync16(sptr(Whp + buf * G0_W + row * 40 + q),
                      Wh_g + (size_t)row * 256 + kt * 32 + q);
        }
        asm volatile("cp.async.commit_group;");
    };

    float acc[8][4];
#pragma unroll
    for (int j = 0; j < 8; j++)
#pragma unroll
        for (int k = 0; k < 4; k++) acc[j][k] = 0.f;

    {
        issueW(0, 0);
        float4 a0 = *(const float4*)&Xf[(size_t)(rb + a_row) * 256 + a_j * 4];
        *(uint2*)&Ahp[a_row * 40 + a_j * 4] =
            make_uint2(pack_f16(a0.x, a0.y), pack_f16(a0.z, a0.w));
        asm volatile("cp.async.wait_group 0;");
    }
    __syncthreads();

#pragma unroll 1
    for (int kt = 0; kt < 8; kt++) {
        const int buf = kt & 1;
        float4 a0;
        if (kt < 7) {
            issueW(kt + 1, buf ^ 1);
            a0 = *(const float4*)&Xf[(size_t)(rb + a_row) * 256 + (kt + 1) * 32 + a_j * 4];
        }
        f16* Ah = Ahp + buf * G0_A;
        f16* Wh = Whp + buf * G0_W;
#pragma unroll
        for (int ks = 0; ks < 2; ks++) {
            uint32_t ah[4];
            {
                int row = wmi * 16 + (lane & 15);
                int kk = ks * 16 + (lane >> 4) * 8;
                ldsm4(ah[0], ah[1], ah[2], ah[3], sptr(&Ah[row * 40 + kk]));
            }
#pragma unroll
            for (int p = 0; p < 4; p++) {
                uint32_t bh[4];
                int row = wn * 64 + p * 16 + ((lane >> 4) << 3) + (lane & 7);
                int kk = ks * 16 + ((lane >> 3) & 1) * 8;
                ldsm4(bh[0], bh[1], bh[2], bh[3], sptr(&Wh[row * 40 + kk]));
                mma16816(acc[2 * p], ah, bh[0], bh[1]);
                mma16816(acc[2 * p + 1], ah, bh[2], bh[3]);
            }
        }
        if (kt < 7) {
            *(uint2*)&Ahp[(buf ^ 1) * G0_A + a_row * 40 + a_j * 4] =
                make_uint2(pack_f16(a0.x, a0.y), pack_f16(a0.z, a0.w));
            asm volatile("cp.async.wait_group 0;");
        }
        __syncthreads();
    }

    // epilogue: scale + scatter to per-group q plane
#pragma unroll
    for (int nt = 0; nt < 8; nt++) {
        int col = wn * 64 + nt * 8 + 2 * (lane & 3);
        int r0 = rb + wmi * 16 + (lane >> 2);
        float b0 = bias[col], b1 = bias[col + 1];
        float v0 = (acc[nt][0] + b0) * SCALE;
        float v1 = (acc[nt][1] + b1) * SCALE;
        float v2 = (acc[nt][2] + b0) * SCALE;
        float v3 = (acc[nt][3] + b1) * SCALE;
        int h = col >> 5, d = col & 31;
        {
            int b = r0 >> 12, s = (r0 >> 3) & 511, vv = r0 & 7;
            int dst = (((h << 3) + vv) * 4 + b) * (SEG * DQ) + s * DQ + d;
            *(uint32_t*)&g_qh[dst] = pack_f16(v0, v1);
        }
        {
            int r1 = r0 + 8;
            int b = r1 >> 12, s = (r1 >> 3) & 511, vv = r1 & 7;
            int dst = (((h << 3) + vv) * 4 + b) * (SEG * DQ) + s * DQ + d;
            *(uint32_t*)&g_qh[dst] = pack_f16(v2, v3);
        }
    }
}

// ---------------------------------------------------------------------------
// gemm1: fc + bias + residual + fused LN. Tile 32 rows x 256 cols (full row
// per CTA), 256 thr (8 warps: 2x4, warp tile 16x64), BK=32, 2-stage,
// 4 CTAs/SM.
// ---------------------------------------------------------------------------
#define G1_A (32 * 40)
#define G1_W (256 * 40)
#define G1_SMEM ((2 * G1_A + 2 * G1_W) * 2)   // 46080

__global__ __launch_bounds__(256, 4) void gemm1(
    const f16* __restrict__ Ah_g, const f16* __restrict__ Wh_g,
    const float* __restrict__ bias, const float* __restrict__ resid,
    const float* __restrict__ gamma, const float* __restrict__ beta,
    float* __restrict__ Cp)
{
    extern __shared__ char smem_raw[];
    f16* Ahp = (f16*)smem_raw;          // [2][32][40]
    f16* Whp = Ahp + 2 * G1_A;          // [2][256][40]

    const int rb = blockIdx.x * 32;
    const int tid = threadIdx.x, lane = tid & 31, w = tid >> 5;
    const int wmi = w & 1, wn = w >> 1;   // 2 (row) x 4 (col)

    auto issue = [&](int kt, int buf) {
#pragma unroll
        for (int u = 0; u < 5; u++) {      // 1152 chunks: 128 A + 1024 W
            int idx = tid + u * 256;
            if (idx < 128) {
                int row = idx >> 2, q = (idx & 3) * 8;
                cpasync16(sptr(Ahp + buf * G1_A + row * 40 + q),
                          Ah_g + (size_t)(rb + row) * 256 + kt * 32 + q);
            } else if (idx < 1152) {
                int i2 = idx - 128;
                int row = i2 >> 2, q = (i2 & 3) * 8;
                cpasync16(sptr(Whp + buf * G1_W + row * 40 + q),
                          Wh_g + (size_t)row * 256 + kt * 32 + q);
            }
        }
        asm volatile("cp.async.commit_group;");
    };

    float acc[8][4];
#pragma unroll
    for (int j = 0; j < 8; j++)
#pragma unroll
        for (int k = 0; k < 4; k++) acc[j][k] = 0.f;

    issue(0, 0);
    asm volatile("cp.async.wait_group 0;");
    __syncthreads();

#pragma unroll 1
    for (int kt = 0; kt < 8; kt++) {
        const int buf = kt & 1;
        if (kt < 7) issue(kt + 1, buf ^ 1);
        f16* Ah = Ahp + buf * G1_A;
        f16* Wh = Whp + buf * G1_W;
#pragma unroll
        for (int ks = 0; ks < 2; ks++) {
            uint32_t ah[4];
            {
                int row = wmi * 16 + (lane & 15);
                int kk = ks * 16 + (lane >> 4) * 8;
                ldsm4(ah[0], ah[1], ah[2], ah[3], sptr(&Ah[row * 40 + kk]));
            }
#pragma unroll
            for (int p = 0; p < 4; p++) {
                uint32_t bh[4];
                int row = wn * 64 + p * 16 + ((lane >> 4) << 3) + (lane & 7);
                int kk = ks * 16 + ((lane >> 3) & 1) * 8;
                ldsm4(bh[0], bh[1], bh[2], bh[3], sptr(&Wh[row * 40 + kk]));
                mma16816(acc[2 * p], ah, bh[0], bh[1]);
                mma16816(acc[2 * p + 1], ah, bh[2], bh[3]);
            }
        }
        asm volatile("cp.async.wait_group 0;");
        __syncthreads();
    }

    // bias + residual + fused LayerNorm over full 256-wide rows
    float2* red = (float2*)smem_raw;                  // [32][4]
    float* mus = (float*)(smem_raw + 2048);           // [32]
    float* rss = (float*)(smem_raw + 2048 + 128);     // [32]

    {
        float s0 = 0.f, q0 = 0.f, s1 = 0.f, q1 = 0.f;
        int rl = wmi * 16 + (lane >> 2);
#pragma unroll
        for (int nt = 0; nt < 8; nt++) {
            int col = wn * 64 + nt * 8 + 2 * (lane & 3);
            float b0 = bias[col], b1 = bias[col + 1];
            float2 rx0 = *(const float2*)&resid[(size_t)(rb + rl) * 256 + col];
            float2 rx1 = *(const float2*)&resid[(size_t)(rb + rl + 8) * 256 + col];
            acc[nt][0] += b0 + rx0.x;
            acc[nt][1] += b1 + rx0.y;
            acc[nt][2] += b0 + rx1.x;
            acc[nt][3] += b1 + rx1.y;
            s0 += acc[nt][0] + acc[nt][1];
            q0 += acc[nt][0] * acc[nt][0] + acc[nt][1] * acc[nt][1];
            s1 += acc[nt][2] + acc[nt][3];
            q1 += acc[nt][2] * acc[nt][2] + acc[nt][3] * acc[nt][3];
        }
#pragma unroll
        for (int o = 1; o <= 2; o <<= 1) {
            s0 += __shfl_xor_sync(0xffffffffu, s0, o);
            q0 += __shfl_xor_sync(0xffffffffu, q0, o);
            s1 += __shfl_xor_sync(0xffffffffu, s1, o);
            q1 += __shfl_xor_sync(0xffffffffu, q1, o);
        }
        if ((lane & 3) == 0) {
            red[rl * 4 + wn] = make_float2(s0, q0);
            red[(rl + 8) * 4 + wn] = make_float2(s1, q1);
        }
    }
    __syncthreads();
    if (tid < 32) {
        float s = 0.f, q = 0.f;
#pragma unroll
        for (int j = 0; j < 4; j++) {
            float2 p = red[tid * 4 + j];
            s += p.x;
            q += p.y;
        }
        float mu = s * (1.f / 256.f);
        float var = q * (1.f / 256.f) - mu * mu;
        mus[tid] = mu;
        rss[tid] = rsqrtf(var + 1e-5f);
    }
    __syncthreads();
#pragma unroll
    for (int nt = 0; nt < 8; nt++) {
        int col = wn * 64 + nt * 8 + 2 * (lane & 3);
        float g0 = gamma[col], g1 = gamma[col + 1];
        float be0 = beta[col], be1 = beta[col + 1];
        int rl = wmi * 16 + (lane >> 2);
        float mu0 = mus[rl], rs0 = rss[rl];
        float mu1 = mus[rl + 8], rs1 = rss[rl + 8];
        float2 o0 = { (acc[nt][0] - mu0) * rs0 * g0 + be0,
                      (acc[nt][1] - mu0) * rs0 * g1 + be1 };
        float2 o1 = { (acc[nt][2] - mu1) * rs1 * g0 + be0,
                      (acc[nt][3] - mu1) * rs1 * g1 + be1 };
        *(float2*)&Cp[(size_t)(rb + rl) * 256 + col] = o0;
        *(float2*)&Cp[(size_t)(rb + rl + 8) * 256 + col] = o1;
    }
}

// ---------------------------------------------------------------------------
// Attention: 4 CTAs/group (128 query rows each), 128 thr (4 warps x 32 rows),
// up to 5 CTAs/SM. z converted fp32->f16 during smem staging.
// ---------------------------------------------------------------------------
struct AttnCtx {
    f16* zh;
    int lane;
    uint32_t qfh[2][2][4];
};

__device__ __forceinline__ void attn_mma1(AttnCtx& c, int ct, float s[2][2][4]) {
#pragma unroll
    for (int i = 0; i < 2; i++)
#pragma unroll
        for (int j = 0; j < 2; j++)
#pragma unroll
            for (int k = 0; k < 4; k++) s[i][j][k] = 0.f;
    const int t0 = ct * 16;
#pragma unroll
    for (int ks = 0; ks < 2; ks++) {
        int zr = t0 + ((c.lane >> 4) << 3) + (c.lane & 7);
        int zk = ks * 16 + ((c.lane >> 3) & 1) * 8;
        uint32_t zbh[4];
        ldsm4(zbh[0], zbh[1], zbh[2], zbh[3], sptr(&c.zh[zr * 40 + zk]));
#pragma unroll
        for (int mt = 0; mt < 2; mt++)
#pragma unroll
            for (int nt = 0; nt < 2; nt++)
                mma16816(s[mt][nt], c.qfh[mt][ks], zbh[nt * 2], zbh[nt * 2 + 1]);
    }
}

__device__ __forceinline__ void attn_softmax(float s[2][2][4], uint32_t pah[2][4],
                                             float dn[2][2]) {
#pragma unroll
    for (int mt = 0; mt < 2; mt++) {
#pragma unroll
        for (int nt = 0; nt < 2; nt++) {
            pah[mt][nt * 2]     = ex2_f16x2(pack_f16(s[mt][nt][0], s[mt][nt][1]));
            pah[mt][nt * 2 + 1] = ex2_f16x2(pack_f16(s[mt][nt][2], s[mt][nt][3]));
        }
        __half2 h0 = __hadd2(*(__half2*)&pah[mt][0], *(__half2*)&pah[mt][2]);
        __half2 h1 = __hadd2(*(__half2*)&pah[mt][1], *(__half2*)&pah[mt][3]);
        float2 f0 = __half22float2(h0);
        float2 f1 = __half22float2(h1);
        dn[mt][0] += f0.x + f0.y;
        dn[mt][1] += f1.x + f1.y;
    }
}

__global__ __launch_bounds__(128, 5) void attn_mma(const float* __restrict__ zf) {
    extern __shared__ __align__(16) f16 zsm[];
    AttnCtx c;
    c.zh = zsm;   // [512][40]

    const int g = blockIdx.x >> 2, quarter = blockIdx.x & 3;
    const int tid = threadIdx.x, w = tid >> 5;
    c.lane = tid & 31;
    const int lane = c.lane;
    const int h = g >> 5, v = (g >> 2) & 7, b = g & 3;

    const float* zg = zf + (size_t)g * SEG * DQ;
#pragma unroll
    for (int u = 0; u < 32; u++) {
        int idx = tid + u * 128;
        int row = idx >> 3, j = idx & 7;
        float4 vz = *(const float4*)&zg[row * 32 + j * 4];
        *(uint2*)&c.zh[row * 40 + j * 4] =
            make_uint2(pack_f16(vz.x, vz.y), pack_f16(vz.z, vz.w));
    }

    const f16* qph = g_qh + (size_t)g * SEG * DQ;
    const int m0 = quarter * 128 + w * 32;
#pragma unroll
    for (int mt = 0; mt < 2; mt++)
#pragma unroll
        for (int ks = 0; ks < 2; ks++) {
            int row = m0 + mt * 16 + (lane >> 2);
            int kk = ks * 16 + 2 * (lane & 3);
            c.qfh[mt][ks][0] = *(const uint32_t*)&qph[row * 32 + kk];
            c.qfh[mt][ks][1] = *(const uint32_t*)&qph[(row + 8) * 32 + kk];
            c.qfh[mt][ks][2] = *(const uint32_t*)&qph[row * 32 + kk + 8];
            c.qfh[mt][ks][3] = *(const uint32_t*)&qph[(row + 8) * 32 + kk + 8];
        }

    float o[2][4][4];
#pragma unroll
    for (int i = 0; i < 2; i++)
#pragma unroll
        for (int j = 0; j < 4; j++)
#pragma unroll
            for (int k = 0; k < 4; k++) o[i][j][k] = 0.f;
    float dn[2][2] = {{0.f, 0.f}, {0.f, 0.f}};

    __syncthreads();

    float s[2][2][4];
    attn_mma1(c, 0, s);

#pragma unroll 1
    for (int ct = 0; ct < 32; ct++) {
        uint32_t zth[2][4];
        const int t0 = ct * 16;
#pragma unroll
        for (int dp = 0; dp < 2; dp++) {
            int zr = t0 + (((lane >> 3) & 1) << 3) + (lane & 7);
            int zc = dp * 16 + (lane >> 4) * 8;
            ldsm4t(zth[dp][0], zth[dp][1], zth[dp][2], zth[dp][3],
                   sptr(&c.zh[zr * 40 + zc]));
        }
        uint32_t pah[2][4];
        attn_softmax(s, pah, dn);
        if (ct < 31) {
            float s2[2][2][4];
            attn_mma1(c, ct + 1, s2);
#pragma unroll
            for (int i = 0; i < 2; i++)
#pragma unroll
                for (int j = 0; j < 2; j++)
#pragma unroll
                    for (int k = 0; k < 4; k++) s[i][j][k] = s2[i][j][k];
        }
#pragma unroll
        for (int dp = 0; dp < 2; dp++)
#pragma unroll
            for (int mt = 0; mt < 2; mt++)
#pragma unroll
                for (int nt = 0; nt < 2; nt++)
                    mma16816(o[mt][dp * 2 + nt], pah[mt],
                             zth[dp][nt * 2], zth[dp][nt * 2 + 1]);
    }

    float inv[2][2];
#pragma unroll
    for (int mt = 0; mt < 2; mt++)
#pragma unroll
        for (int rh = 0; rh < 2; rh++) {
            float d = dn[mt][rh];
            d += __shfl_xor_sync(0xffffffffu, d, 1);
            d += __shfl_xor_sync(0xffffffffu, d, 2);
            inv[mt][rh] = __fdividef(1.f, d);
        }

#pragma unroll
    for (int mt = 0; mt < 2; mt++) {
        int s0 = m0 + mt * 16 + (lane >> 2);
        int r0 = ((b * SEG + s0) * 8) + v;
        int r1 = ((b * SEG + s0 + 8) * 8) + v;
#pragma unroll
        for (int n = 0; n < 4; n++) {
            int col = h * 32 + n * 8 + 2 * (lane & 3);
            *(uint32_t*)&g_oh[(size_t)r0 * 256 + col] =
                pack_f16(o[mt][n][0] * inv[mt][0], o[mt][n][1] * inv[mt][0]);
            *(uint32_t*)&g_oh[(size_t)r1 * 256 + col] =
                pack_f16(o[mt][n][2] * inv[mt][1], o[mt][n][3] * inv[mt][1]);
        }
    }
}

// ---------------------------------------------------------------------------

extern "C" void kernel_launch(void* const* d_in, const int* in_sizes, int n_in,
                              void* d_out, int out_size)
{
    const float* x     = (const float*)d_in[0];
    const float* z     = (const float*)d_in[1];
    const float* wq    = (const float*)d_in[2];
    const float* wqb   = (const float*)d_in[3];
    const float* fcw   = (const float*)d_in[4];
    const float* fcb   = (const float*)d_in[5];
    const float* gamma = (const float*)d_in[6];
    const float* beta  = (const float*)d_in[7];
    float* y = (float*)d_out;

    static f16 *oh_p = nullptr, *wqh_p, *fh_p;
    if (!oh_p) {
        cudaGetSymbolAddress((void**)&oh_p, g_oh);
        cudaGetSymbolAddress((void**)&wqh_p, g_wqh);
        cudaGetSymbolAddress((void**)&fh_p, g_fh);
        cudaFuncSetAttribute(gemm0, cudaFuncAttributeMaxDynamicSharedMemorySize, G0_SMEM);
        cudaFuncSetAttribute(gemm1, cudaFuncAttributeMaxDynamicSharedMemorySize, G1_SMEM);
        cudaFuncSetAttribute(attn_mma, cudaFuncAttributeMaxDynamicSharedMemorySize, 512 * 40 * 2);
    }

    prep<<<128, 256>>>(wq, fcw);
    gemm0<<<512, 256, G0_SMEM>>>(x, wqh_p, wqb);
    attn_mma<<<NG * 4, 128, 512 * 40 * 2>>>(z);
    gemm1<<<512, 256, G1_SMEM>>>(oh_p, fh_p, fcb, x, gamma, beta, y);
}

// round 15
// speedup vs baseline: 1.1769x; 1.1769x over previous
#include <cuda_runtime.h>
#include <cuda_fp16.h>
#include <cstdint>

// ---------------------------------------------------------------------------
// bs=4 seg=512 nv=8 h=8 dq=32 din=256; tokens=16384, groups=256
// ALL-FP16 datapath. R15 = R12 config + BK=64 k-tiles in both GEMMs
// (halves barrier/wait count; L1TEX work per FLOP unchanged).
//  prep  : Wq, fc -> fp16 planes
//  gemm0 : q = (x@WqT + b)*log2e/temp; 64x256 tile, fp32 x reg-prefetch
//  attn  : 4 CTAs/group (128 rows, 128 thr, occ5); z cvt during staging
//  gemm1 : fc + bias + residual + fused LN; 64x256 tile, occ2
// ---------------------------------------------------------------------------

#define NTOK 16384
#define SEG  512
#define DQ   32
#define NG   256
#define SCALE 0.2550353055731662f   // log2(e)/sqrt(32)

typedef __half f16;

__device__ f16 g_qh[NG * SEG * DQ];
__device__ f16 g_oh[NTOK * 256];
__device__ f16 g_wqh[256 * 256];
__device__ f16 g_fh[256 * 256];

// ---------------- helpers ----------------
__device__ __forceinline__ uint32_t sptr(const void* p) {
    return (uint32_t)__cvta_generic_to_shared(p);
}
__device__ __forceinline__ void ldsm4(uint32_t& r0, uint32_t& r1, uint32_t& r2,
                                      uint32_t& r3, uint32_t a) {
    asm volatile("ldmatrix.sync.aligned.m8n8.x4.shared.b16 {%0,%1,%2,%3}, [%4];"
                 : "=r"(r0), "=r"(r1), "=r"(r2), "=r"(r3) : "r"(a));
}
__device__ __forceinline__ void ldsm4t(uint32_t& r0, uint32_t& r1, uint32_t& r2,
                                       uint32_t& r3, uint32_t a) {
    asm volatile("ldmatrix.sync.aligned.m8n8.x4.trans.shared.b16 {%0,%1,%2,%3}, [%4];"
                 : "=r"(r0), "=r"(r1), "=r"(r2), "=r"(r3) : "r"(a));
}
__device__ __forceinline__ void mma16816(float* d, const uint32_t* a,
                                         uint32_t b0, uint32_t b1) {
    asm volatile(
        "mma.sync.aligned.m16n8k16.row.col.f32.f16.f16.f32 "
        "{%0,%1,%2,%3}, {%4,%5,%6,%7}, {%8,%9}, {%0,%1,%2,%3};"
        : "+f"(d[0]), "+f"(d[1]), "+f"(d[2]), "+f"(d[3])
        : "r"(a[0]), "r"(a[1]), "r"(a[2]), "r"(a[3]), "r"(b0), "r"(b1));
}
__device__ __forceinline__ uint32_t pack_f16(float x, float y) {
    __half2 h = __floats2half2_rn(x, y);
    return *(uint32_t*)&h;
}
__device__ __forceinline__ uint32_t ex2_f16x2(uint32_t a) {
    uint32_t r;
    asm("ex2.approx.f16x2 %0, %1;" : "=r"(r) : "r"(a));
    return r;
}
__device__ __forceinline__ void cpasync16(uint32_t dst, const void* src) {
    asm volatile("cp.async.ca.shared.global [%0], [%1], 16;" :: "r"(dst), "l"(src));
}

// ---------------- prep: weights fp32 -> fp16 ----------------
__global__ __launch_bounds__(256) void prep(const float* __restrict__ wq,
                                            const float* __restrict__ fcw) {
    int blk = blockIdx.x;
    const float* src = (blk < 64) ? wq : fcw;
    f16* dh = (blk < 64) ? g_wqh : g_fh;
    int i = ((blk < 64) ? blk : blk - 64) * 256 + threadIdx.x;
    float4 v = ((const float4*)src)[i];
    ((uint2*)dh)[i] = make_uint2(pack_f16(v.x, v.y), pack_f16(v.z, v.w));
}

// ---------------------------------------------------------------------------
// gemm0: q-projection, fused x conversion. Tile 64 rows x 256 cols, 256 thr
// (8 warps 2x4, warp 32x64), BK=64 (4 k-tiles), 2-stage. 2 CTAs/SM.
// A: fp32 LDG + cvt + STS reg-prefetch (4 float4/thr); W: fp16 cp.async.
// ---------------------------------------------------------------------------
#define G0_A (64 * 72)                  // halves per A stage
#define G0_W (256 * 72)
#define G0_SMEM ((2 * G0_A + 2 * G0_W) * 2)   // 92160

__global__ __launch_bounds__(256, 2) void gemm0(
    const float* __restrict__ Xf, const f16* __restrict__ Wh_g,
    const float* __restrict__ bias)
{
    extern __shared__ char smem_raw[];
    f16* Ahp = (f16*)smem_raw;          // [2][64][72]
    f16* Whp = Ahp + 2 * G0_A;          // [2][256][72]

    const int rb = blockIdx.x * 64;
    const int tid = threadIdx.x, lane = tid & 31, w = tid >> 5;
    const int wmi = w & 1, wn = w >> 1;   // 2 (row) x 4 (col)

    auto issueW = [&](int kt, int buf) {
#pragma unroll
        for (int u = 0; u < 8; u++) {          // 2048 16B chunks
            int idx = tid + u * 256;
            int row = idx >> 3, q = (idx & 7) * 8;
            cpasync16(sptr(Whp + buf * G0_W + row * 72 + q),
                      Wh_g + (size_t)row * 256 + kt * 64 + q);
        }
        asm volatile("cp.async.commit_group;");
    };
    auto loadA = [&](int kt, float4* av) {
#pragma unroll
        for (int u = 0; u < 4; u++) {          // 1024 float4 chunks
            int c = tid + u * 256;
            int row = c >> 4, j = c & 15;
            av[u] = *(const float4*)&Xf[(size_t)(rb + row) * 256 + kt * 64 + j * 4];
        }
    };
    auto storeA = [&](int buf, const float4* av) {
#pragma unroll
        for (int u = 0; u < 4; u++) {
            int c = tid + u * 256;
            int row = c >> 4, j = c & 15;
            *(uint2*)&Ahp[buf * G0_A + row * 72 + j * 4] =
                make_uint2(pack_f16(av[u].x, av[u].y), pack_f16(av[u].z, av[u].w));
        }
    };

    float acc[2][8][4];
#pragma unroll
    for (int i = 0; i < 2; i++)
#pragma unroll
        for (int j = 0; j < 8; j++)
#pragma unroll
            for (int k = 0; k < 4; k++) acc[i][j][k] = 0.f;

    {
        issueW(0, 0);
        float4 av[4];
        loadA(0, av);
        storeA(0, av);
        asm volatile("cp.async.wait_group 0;");
    }
    __syncthreads();

#pragma unroll 1
    for (int kt = 0; kt < 4; kt++) {
        const int buf = kt & 1;
        float4 av[4];
        if (kt < 3) {
            issueW(kt + 1, buf ^ 1);
            loadA(kt + 1, av);
        }
        f16* Ah = Ahp + buf * G0_A;
        f16* Wh = Whp + buf * G0_W;
#pragma unroll
        for (int ks = 0; ks < 4; ks++) {
            uint32_t bh[4][4];
#pragma unroll
            for (int p = 0; p < 4; p++) {
                int row = wn * 64 + p * 16 + ((lane >> 4) << 3) + (lane & 7);
                int kk = ks * 16 + ((lane >> 3) & 1) * 8;
                ldsm4(bh[p][0], bh[p][1], bh[p][2], bh[p][3], sptr(&Wh[row * 72 + kk]));
            }
#pragma unroll
            for (int mt = 0; mt < 2; mt++) {
                int row = wmi * 32 + mt * 16 + (lane & 15);
                int kk = ks * 16 + (lane >> 4) * 8;
                uint32_t ah[4];
                ldsm4(ah[0], ah[1], ah[2], ah[3], sptr(&Ah[row * 72 + kk]));
#pragma unroll
                for (int nt = 0; nt < 8; nt++) {
                    int p = nt >> 1, q = (nt & 1) * 2;
                    mma16816(acc[mt][nt], ah, bh[p][q], bh[p][q + 1]);
                }
            }
        }
        if (kt < 3) {
            storeA(buf ^ 1, av);
            asm volatile("cp.async.wait_group 0;");
        }
        __syncthreads();
    }

    // epilogue: scale + scatter to per-group q plane
#pragma unroll
    for (int mt = 0; mt < 2; mt++) {
#pragma unroll
        for (int nt = 0; nt < 8; nt++) {
            int col = wn * 64 + nt * 8 + 2 * (lane & 3);
            int r0 = rb + wmi * 32 + mt * 16 + (lane >> 2);
            float b0 = bias[col], b1 = bias[col + 1];
            float v0 = (acc[mt][nt][0] + b0) * SCALE;
            float v1 = (acc[mt][nt][1] + b1) * SCALE;
            float v2 = (acc[mt][nt][2] + b0) * SCALE;
            float v3 = (acc[mt][nt][3] + b1) * SCALE;
            int h = col >> 5, d = col & 31;
            {
                int b = r0 >> 12, s = (r0 >> 3) & 511, vv = r0 & 7;
                int dst = (((h << 3) + vv) * 4 + b) * (SEG * DQ) + s * DQ + d;
                *(uint32_t*)&g_qh[dst] = pack_f16(v0, v1);
            }
            {
                int r1 = r0 + 8;
                int b = r1 >> 12, s = (r1 >> 3) & 511, vv = r1 & 7;
                int dst = (((h << 3) + vv) * 4 + b) * (SEG * DQ) + s * DQ + d;
                *(uint32_t*)&g_qh[dst] = pack_f16(v2, v3);
            }
        }
    }
}

// ---------------------------------------------------------------------------
// gemm1: fc + bias + residual + fused LN. Tile 64x256 (full row per CTA),
// 256 thr (8 warps 2x4, warp 32x64), BK=64 (4 k-tiles), 2-stage, 2 CTAs/SM.
// ---------------------------------------------------------------------------
#define G1_A (64 * 72)
#define G1_W (256 * 72)
#define G1_SMEM ((2 * G1_A + 2 * G1_W) * 2)   // 92160

__global__ __launch_bounds__(256, 2) void gemm1(
    const f16* __restrict__ Ah_g, const f16* __restrict__ Wh_g,
    const float* __restrict__ bias, const float* __restrict__ resid,
    const float* __restrict__ gamma, const float* __restrict__ beta,
    float* __restrict__ Cp)
{
    extern __shared__ char smem_raw[];
    f16* Ahp = (f16*)smem_raw;          // [2][64][72]
    f16* Whp = Ahp + 2 * G1_A;          // [2][256][72]

    const int rb = blockIdx.x * 64;
    const int tid = threadIdx.x, lane = tid & 31, w = tid >> 5;
    const int wmi = w & 1, wn = w >> 1;   // 2 (row) x 4 (col)

    auto issue = [&](int kt, int buf) {
#pragma unroll
        for (int u = 0; u < 10; u++) {     // 2560 chunks: 512 A + 2048 W
            int idx = tid + u * 256;
            if (idx < 512) {
                int row = idx >> 3, q = (idx & 7) * 8;
                cpasync16(sptr(Ahp + buf * G1_A + row * 72 + q),
                          Ah_g + (size_t)(rb + row) * 256 + kt * 64 + q);
            } else {
                int i2 = idx - 512;
                int row = i2 >> 3, q = (i2 & 7) * 8;
                cpasync16(sptr(Whp + buf * G1_W + row * 72 + q),
                          Wh_g + (size_t)row * 256 + kt * 64 + q);
            }
        }
        asm volatile("cp.async.commit_group;");
    };

    float acc[2][8][4];
#pragma unroll
    for (int i = 0; i < 2; i++)
#pragma unroll
        for (int j = 0; j < 8; j++)
#pragma unroll
            for (int k = 0; k < 4; k++) acc[i][j][k] = 0.f;

    issue(0, 0);
    asm volatile("cp.async.wait_group 0;");
    __syncthreads();

#pragma unroll 1
    for (int kt = 0; kt < 4; kt++) {
        const int buf = kt & 1;
        if (kt < 3) issue(kt + 1, buf ^ 1);
        f16* Ah = Ahp + buf * G1_A;
        f16* Wh = Whp + buf * G1_W;
#pragma unroll
        for (int ks = 0; ks < 4; ks++) {
            uint32_t bh[4][4];
#pragma unroll
            for (int p = 0; p < 4; p++) {
                int row = wn * 64 + p * 16 + ((lane >> 4) << 3) + (lane & 7);
                int kk = ks * 16 + ((lane >> 3) & 1) * 8;
                ldsm4(bh[p][0], bh[p][1], bh[p][2], bh[p][3], sptr(&Wh[row * 72 + kk]));
            }
#pragma unroll
            for (int mt = 0; mt < 2; mt++) {
                int row = wmi * 32 + mt * 16 + (lane & 15);
                int kk = ks * 16 + (lane >> 4) * 8;
                uint32_t ah[4];
                ldsm4(ah[0], ah[1], ah[2], ah[3], sptr(&Ah[row * 72 + kk]));
#pragma unroll
                for (int nt = 0; nt < 8; nt++) {
                    int p = nt >> 1, q = (nt & 1) * 2;
                    mma16816(acc[mt][nt], ah, bh[p][q], bh[p][q + 1]);
                }
            }
        }
        asm volatile("cp.async.wait_group 0;");
        __syncthreads();
    }

    // bias + residual + fused LayerNorm over full 256-wide rows
    float2* red = (float2*)smem_raw;                  // [64][4]
    float* mus = (float*)(smem_raw + 4096);           // [64]
    float* rss = (float*)(smem_raw + 4096 + 256);     // [64]

#pragma unroll
    for (int mt = 0; mt < 2; mt++) {
        float s0 = 0.f, q0 = 0.f, s1 = 0.f, q1 = 0.f;
        int rl = wmi * 32 + mt * 16 + (lane >> 2);
#pragma unroll
        for (int nt = 0; nt < 8; nt++) {
            int col = wn * 64 + nt * 8 + 2 * (lane & 3);
            float b0 = bias[col], b1 = bias[col + 1];
            float2 rx0 = *(const float2*)&resid[(size_t)(rb + rl) * 256 + col];
            float2 rx1 = *(const float2*)&resid[(size_t)(rb + rl + 8) * 256 + col];
            acc[mt][nt][0] += b0 + rx0.x;
            acc[mt][nt][1] += b1 + rx0.y;
            acc[mt][nt][2] += b0 + rx1.x;
            acc[mt][nt][3] += b1 + rx1.y;
            s0 += acc[mt][nt][0] + acc[mt][nt][1];
            q0 += acc[mt][nt][0] * acc[mt][nt][0] + acc[mt][nt][1] * acc[mt][nt][1];
            s1 += acc[mt][nt][2] + acc[mt][nt][3];
            q1 += acc[mt][nt][2] * acc[mt][nt][2] + acc[mt][nt][3] * acc[mt][nt][3];
        }
#pragma unroll
        for (int o = 1; o <= 2; o <<= 1) {
            s0 += __shfl_xor_sync(0xffffffffu, s0, o);
            q0 += __shfl_xor_sync(0xffffffffu, q0, o);
            s1 += __shfl_xor_sync(0xffffffffu, s1, o);
            q1 += __shfl_xor_sync(0xffffffffu, q1, o);
        }
        if ((lane & 3) == 0) {
            red[rl * 4 + wn] = make_float2(s0, q0);
            red[(rl + 8) * 4 + wn] = make_float2(s1, q1);
        }
    }
    __syncthreads();
    if (tid < 64) {
        float s = 0.f, q = 0.f;
#pragma unroll
        for (int j = 0; j < 4; j++) {
            float2 p = red[tid * 4 + j];
            s += p.x;
            q += p.y;
        }
        float mu = s * (1.f / 256.f);
        float var = q * (1.f / 256.f) - mu * mu;
        mus[tid] = mu;
        rss[tid] = rsqrtf(var + 1e-5f);
    }
    __syncthreads();
#pragma unroll
    for (int nt = 0; nt < 8; nt++) {
        int col = wn * 64 + nt * 8 + 2 * (lane & 3);
        float g0 = gamma[col], g1 = gamma[col + 1];
        float be0 = beta[col], be1 = beta[col + 1];
#pragma unroll
        for (int mt = 0; mt < 2; mt++) {
            int rl = wmi * 32 + mt * 16 + (lane >> 2);
            float mu0 = mus[rl], rs0 = rss[rl];
            float mu1 = mus[rl + 8], rs1 = rss[rl + 8];
            float2 o0 = { (acc[mt][nt][0] - mu0) * rs0 * g0 + be0,
                          (acc[mt][nt][1] - mu0) * rs0 * g1 + be1 };
            float2 o1 = { (acc[mt][nt][2] - mu1) * rs1 * g0 + be0,
                          (acc[mt][nt][3] - mu1) * rs1 * g1 + be1 };
            *(float2*)&Cp[(size_t)(rb + rl) * 256 + col] = o0;
            *(float2*)&Cp[(size_t)(rb + rl + 8) * 256 + col] = o1;
        }
    }
}

// ---------------------------------------------------------------------------
// Attention (frozen at R12): 4 CTAs/group, 128 thr, occ5, z cvt in staging.
// ---------------------------------------------------------------------------
struct AttnCtx {
    f16* zh;
    int lane;
    uint32_t qfh[2][2][4];
};

__device__ __forceinline__ void attn_mma1(AttnCtx& c, int ct, float s[2][2][4]) {
#pragma unroll
    for (int i = 0; i < 2; i++)
#pragma unroll
        for (int j = 0; j < 2; j++)
#pragma unroll
            for (int k = 0; k < 4; k++) s[i][j][k] = 0.f;
    const int t0 = ct * 16;
#pragma unroll
    for (int ks = 0; ks < 2; ks++) {
        int zr = t0 + ((c.lane >> 4) << 3) + (c.lane & 7);
        int zk = ks * 16 + ((c.lane >> 3) & 1) * 8;
        uint32_t zbh[4];
        ldsm4(zbh[0], zbh[1], zbh[2], zbh[3], sptr(&c.zh[zr * 40 + zk]));
#pragma unroll
        for (int mt = 0; mt < 2; mt++)
#pragma unroll
            for (int nt = 0; nt < 2; nt++)
                mma16816(s[mt][nt], c.qfh[mt][ks], zbh[nt * 2], zbh[nt * 2 + 1]);
    }
}

__device__ __forceinline__ void attn_softmax(float s[2][2][4], uint32_t pah[2][4],
                                             float dn[2][2]) {
#pragma unroll
    for (int mt = 0; mt < 2; mt++) {
#pragma unroll
        for (int nt = 0; nt < 2; nt++) {
            pah[mt][nt * 2]     = ex2_f16x2(pack_f16(s[mt][nt][0], s[mt][nt][1]));
            pah[mt][nt * 2 + 1] = ex2_f16x2(pack_f16(s[mt][nt][2], s[mt][nt][3]));
        }
        __half2 h0 = __hadd2(*(__half2*)&pah[mt][0], *(__half2*)&pah[mt][2]);
        __half2 h1 = __hadd2(*(__half2*)&pah[mt][1], *(__half2*)&pah[mt][3]);
        float2 f0 = __half22float2(h0);
        float2 f1 = __half22float2(h1);
        dn[mt][0] += f0.x + f0.y;
        dn[mt][1] += f1.x + f1.y;
    }
}

__global__ __launch_bounds__(128, 5) void attn_mma(const float* __restrict__ zf) {
    extern __shared__ __align__(16) f16 zsm[];
    AttnCtx c;
    c.zh = zsm;   // [512][40]

    const int g = blockIdx.x >> 2, quarter = blockIdx.x & 3;
    const int tid = threadIdx.x, w = tid >> 5;
    c.lane = tid & 31;
    const int lane = c.lane;
    const int h = g >> 5, v = (g >> 2) & 7, b = g & 3;

    const float* zg = zf + (size_t)g * SEG * DQ;
#pragma unroll
    for (int u = 0; u < 32; u++) {
        int idx = tid + u * 128;
        int row = idx >> 3, j = idx & 7;
        float4 vz = *(const float4*)&zg[row * 32 + j * 4];
        *(uint2*)&c.zh[row * 40 + j * 4] =
            make_uint2(pack_f16(vz.x, vz.y), pack_f16(vz.z, vz.w));
    }

    const f16* qph = g_qh + (size_t)g * SEG * DQ;
    const int m0 = quarter * 128 + w * 32;
#pragma unroll
    for (int mt = 0; mt < 2; mt++)
#pragma unroll
        for (int ks = 0; ks < 2; ks++) {
            int row = m0 + mt * 16 + (lane >> 2);
            int kk = ks * 16 + 2 * (lane & 3);
            c.qfh[mt][ks][0] = *(const uint32_t*)&qph[row * 32 + kk];
            c.qfh[mt][ks][1] = *(const uint32_t*)&qph[(row + 8) * 32 + kk];
            c.qfh[mt][ks][2] = *(const uint32_t*)&qph[row * 32 + kk + 8];
            c.qfh[mt][ks][3] = *(const uint32_t*)&qph[(row + 8) * 32 + kk + 8];
        }

    float o[2][4][4];
#pragma unroll
    for (int i = 0; i < 2; i++)
#pragma unroll
        for (int j = 0; j < 4; j++)
#pragma unroll
            for (int k = 0; k < 4; k++) o[i][j][k] = 0.f;
    float dn[2][2] = {{0.f, 0.f}, {0.f, 0.f}};

    __syncthreads();

    float s[2][2][4];
    attn_mma1(c, 0, s);

#pragma unroll 1
    for (int ct = 0; ct < 32; ct++) {
        uint32_t zth[2][4];
        const int t0 = ct * 16;
#pragma unroll
        for (int dp = 0; dp < 2; dp++) {
            int zr = t0 + (((lane >> 3) & 1) << 3) + (lane & 7);
            int zc = dp * 16 + (lane >> 4) * 8;
            ldsm4t(zth[dp][0], zth[dp][1], zth[dp][2], zth[dp][3],
                   sptr(&c.zh[zr * 40 + zc]));
        }
        uint32_t pah[2][4];
        attn_softmax(s, pah, dn);
        if (ct < 31) {
            float s2[2][2][4];
            attn_mma1(c, ct + 1, s2);
#pragma unroll
            for (int i = 0; i < 2; i++)
#pragma unroll
                for (int j = 0; j < 2; j++)
#pragma unroll
                    for (int k = 0; k < 4; k++) s[i][j][k] = s2[i][j][k];
        }
#pragma unroll
        for (int dp = 0; dp < 2; dp++)
#pragma unroll
            for (int mt = 0; mt < 2; mt++)
#pragma unroll
                for (int nt = 0; nt < 2; nt++)
                    mma16816(o[mt][dp * 2 + nt], pah[mt],
                             zth[dp][nt * 2], zth[dp][nt * 2 + 1]);
    }

    float inv[2][2];
#pragma unroll
    for (int mt = 0; mt < 2; mt++)
#pragma unroll
        for (int rh = 0; rh < 2; rh++) {
            float d = dn[mt][rh];
            d += __shfl_xor_sync(0xffffffffu, d, 1);
            d += __shfl_xor_sync(0xffffffffu, d, 2);
            inv[mt][rh] = __fdividef(1.f, d);
        }

#pragma unroll
    for (int mt = 0; mt < 2; mt++) {
        int s0 = m0 + mt * 16 + (lane >> 2);
        int r0 = ((b * SEG + s0) * 8) + v;
        int r1 = ((b * SEG + s0 + 8) * 8) + v;
#pragma unroll
        for (int n = 0; n < 4; n++) {
            int col = h * 32 + n * 8 + 2 * (lane & 3);
            *(uint32_t*)&g_oh[(size_t)r0 * 256 + col] =
                pack_f16(o[mt][n][0] * inv[mt][0], o[mt][n][1] * inv[mt][0]);
            *(uint32_t*)&g_oh[(size_t)r1 * 256 + col] =
                pack_f16(o[mt][n][2] * inv[mt][1], o[mt][n][3] * inv[mt][1]);
        }
    }
}

// ---------------------------------------------------------------------------

extern "C" void kernel_launch(void* const* d_in, const int* in_sizes, int n_in,
                              void* d_out, int out_size)
{
    const float* x     = (const float*)d_in[0];
    const float* z     = (const float*)d_in[1];
    const float* wq    = (const float*)d_in[2];
    const float* wqb   = (const float*)d_in[3];
    const float* fcw   = (const float*)d_in[4];
    const float* fcb   = (const float*)d_in[5];
    const float* gamma = (const float*)d_in[6];
    const float* beta  = (const float*)d_in[7];
    float* y = (float*)d_out;

    static f16 *oh_p = nullptr, *wqh_p, *fh_p;
    if (!oh_p) {
        cudaGetSymbolAddress((void**)&oh_p, g_oh);
        cudaGetSymbolAddress((void**)&wqh_p, g_wqh);
        cudaGetSymbolAddress((void**)&fh_p, g_fh);
        cudaFuncSetAttribute(gemm0, cudaFuncAttributeMaxDynamicSharedMemorySize, G0_SMEM);
        cudaFuncSetAttribute(gemm1, cudaFuncAttributeMaxDynamicSharedMemorySize, G1_SMEM);
        cudaFuncSetAttribute(attn_mma, cudaFuncAttributeMaxDynamicSharedMemorySize, 512 * 40 * 2);
    }

    prep<<<128, 256>>>(wq, fcw);
    gemm0<<<256, 256, G0_SMEM>>>(x, wqh_p, wqb);
    attn_mma<<<NG * 4, 128, 512 * 40 * 2>>>(z);
    gemm1<<<256, 256, G1_SMEM>>>(oh_p, fh_p, fcb, x, gamma, beta, y);
}

// round 16
// speedup vs baseline: 1.1814x; 1.0039x over previous
#include <cuda_runtime.h>
#include <cuda_fp16.h>
#include <cstdint>

// ---------------------------------------------------------------------------
// bs=4 seg=512 nv=8 h=8 dq=32 din=256; tokens=16384, groups=256
// ALL-FP16 datapath. R16 = R15 + attn MMA1 in f16-accumulate (2x HMMA rate,
// output already packed for ex2.f16x2 -- pack cvts deleted).
//  prep  : Wq, fc -> fp16 planes
//  gemm0 : q = (x@WqT + b)*log2e/temp; 64x256 tile, BK=64, fp32 x prefetch
//  attn  : 4 CTAs/group (128 rows, 128 thr, occ5); MMA1 f16-acc, ex2.f16x2,
//          MMA2 f32-acc
//  gemm1 : fc + bias + residual + fused LN; 64x256 tile, BK=64, occ2
// ---------------------------------------------------------------------------

#define NTOK 16384
#define SEG  512
#define DQ   32
#define NG   256
#define SCALE 0.2550353055731662f   // log2(e)/sqrt(32)

typedef __half f16;

__device__ f16 g_qh[NG * SEG * DQ];
__device__ f16 g_oh[NTOK * 256];
__device__ f16 g_wqh[256 * 256];
__device__ f16 g_fh[256 * 256];

// ---------------- helpers ----------------
__device__ __forceinline__ uint32_t sptr(const void* p) {
    return (uint32_t)__cvta_generic_to_shared(p);
}
__device__ __forceinline__ void ldsm4(uint32_t& r0, uint32_t& r1, uint32_t& r2,
                                      uint32_t& r3, uint32_t a) {
    asm volatile("ldmatrix.sync.aligned.m8n8.x4.shared.b16 {%0,%1,%2,%3}, [%4];"
                 : "=r"(r0), "=r"(r1), "=r"(r2), "=r"(r3) : "r"(a));
}
__device__ __forceinline__ void ldsm4t(uint32_t& r0, uint32_t& r1, uint32_t& r2,
                                       uint32_t& r3, uint32_t a) {
    asm volatile("ldmatrix.sync.aligned.m8n8.x4.trans.shared.b16 {%0,%1,%2,%3}, [%4];"
                 : "=r"(r0), "=r"(r1), "=r"(r2), "=r"(r3) : "r"(a));
}
__device__ __forceinline__ void mma16816(float* d, const uint32_t* a,
                                         uint32_t b0, uint32_t b1) {
    asm volatile(
        "mma.sync.aligned.m16n8k16.row.col.f32.f16.f16.f32 "
        "{%0,%1,%2,%3}, {%4,%5,%6,%7}, {%8,%9}, {%0,%1,%2,%3};"
        : "+f"(d[0]), "+f"(d[1]), "+f"(d[2]), "+f"(d[3])
        : "r"(a[0]), "r"(a[1]), "r"(a[2]), "r"(a[3]), "r"(b0), "r"(b1));
}
// f16-accumulate variant: D packed as 2x f16x2 regs -- 2x rate, softmax-ready
__device__ __forceinline__ void mma16816_h(uint32_t* d, const uint32_t* a,
                                           uint32_t b0, uint32_t b1) {
    asm volatile(
        "mma.sync.aligned.m16n8k16.row.col.f16.f16.f16.f16 "
        "{%0,%1}, {%2,%3,%4,%5}, {%6,%7}, {%0,%1};"
        : "+r"(d[0]), "+r"(d[1])
        : "r"(a[0]), "r"(a[1]), "r"(a[2]), "r"(a[3]), "r"(b0), "r"(b1));
}
__device__ __forceinline__ uint32_t pack_f16(float x, float y) {
    __half2 h = __floats2half2_rn(x, y);
    return *(uint32_t*)&h;
}
__device__ __forceinline__ uint32_t ex2_f16x2(uint32_t a) {
    uint32_t r;
    asm("ex2.approx.f16x2 %0, %1;" : "=r"(r) : "r"(a));
    return r;
}
__device__ __forceinline__ void cpasync16(uint32_t dst, const void* src) {
    asm volatile("cp.async.ca.shared.global [%0], [%1], 16;" :: "r"(dst), "l"(src));
}

// ---------------- prep: weights fp32 -> fp16 ----------------
__global__ __launch_bounds__(256) void prep(const float* __restrict__ wq,
                                            const float* __restrict__ fcw) {
    int blk = blockIdx.x;
    const float* src = (blk < 64) ? wq : fcw;
    f16* dh = (blk < 64) ? g_wqh : g_fh;
    int i = ((blk < 64) ? blk : blk - 64) * 256 + threadIdx.x;
    float4 v = ((const float4*)src)[i];
    ((uint2*)dh)[i] = make_uint2(pack_f16(v.x, v.y), pack_f16(v.z, v.w));
}

// ---------------------------------------------------------------------------
// gemm0: q-projection, fused x conversion. 64x256 tile, 256 thr, BK=64,
// 2-stage, 2 CTAs/SM. (R15 config, unchanged)
// ---------------------------------------------------------------------------
#define G0_A (64 * 72)
#define G0_W (256 * 72)
#define G0_SMEM ((2 * G0_A + 2 * G0_W) * 2)   // 92160

__global__ __launch_bounds__(256, 2) void gemm0(
    const float* __restrict__ Xf, const f16* __restrict__ Wh_g,
    const float* __restrict__ bias)
{
    extern __shared__ char smem_raw[];
    f16* Ahp = (f16*)smem_raw;          // [2][64][72]
    f16* Whp = Ahp + 2 * G0_A;          // [2][256][72]

    const int rb = blockIdx.x * 64;
    const int tid = threadIdx.x, lane = tid & 31, w = tid >> 5;
    const int wmi = w & 1, wn = w >> 1;

    auto issueW = [&](int kt, int buf) {
#pragma unroll
        for (int u = 0; u < 8; u++) {
            int idx = tid + u * 256;
            int row = idx >> 3, q = (idx & 7) * 8;
            cpasync16(sptr(Whp + buf * G0_W + row * 72 + q),
                      Wh_g + (size_t)row * 256 + kt * 64 + q);
        }
        asm volatile("cp.async.commit_group;");
    };
    auto loadA = [&](int kt, float4* av) {
#pragma unroll
        for (int u = 0; u < 4; u++) {
            int c = tid + u * 256;
            int row = c >> 4, j = c & 15;
            av[u] = *(const float4*)&Xf[(size_t)(rb + row) * 256 + kt * 64 + j * 4];
        }
    };
    auto storeA = [&](int buf, const float4* av) {
#pragma unroll
        for (int u = 0; u < 4; u++) {
            int c = tid + u * 256;
            int row = c >> 4, j = c & 15;
            *(uint2*)&Ahp[buf * G0_A + row * 72 + j * 4] =
                make_uint2(pack_f16(av[u].x, av[u].y), pack_f16(av[u].z, av[u].w));
        }
    };

    float acc[2][8][4];
#pragma unroll
    for (int i = 0; i < 2; i++)
#pragma unroll
        for (int j = 0; j < 8; j++)
#pragma unroll
            for (int k = 0; k < 4; k++) acc[i][j][k] = 0.f;

    {
        issueW(0, 0);
        float4 av[4];
        loadA(0, av);
        storeA(0, av);
        asm volatile("cp.async.wait_group 0;");
    }
    __syncthreads();

#pragma unroll 1
    for (int kt = 0; kt < 4; kt++) {
        const int buf = kt & 1;
        float4 av[4];
        if (kt < 3) {
            issueW(kt + 1, buf ^ 1);
            loadA(kt + 1, av);
        }
        f16* Ah = Ahp + buf * G0_A;
        f16* Wh = Whp + buf * G0_W;
#pragma unroll
        for (int ks = 0; ks < 4; ks++) {
            uint32_t bh[4][4];
#pragma unroll
            for (int p = 0; p < 4; p++) {
                int row = wn * 64 + p * 16 + ((lane >> 4) << 3) + (lane & 7);
                int kk = ks * 16 + ((lane >> 3) & 1) * 8;
                ldsm4(bh[p][0], bh[p][1], bh[p][2], bh[p][3], sptr(&Wh[row * 72 + kk]));
            }
#pragma unroll
            for (int mt = 0; mt < 2; mt++) {
                int row = wmi * 32 + mt * 16 + (lane & 15);
                int kk = ks * 16 + (lane >> 4) * 8;
                uint32_t ah[4];
                ldsm4(ah[0], ah[1], ah[2], ah[3], sptr(&Ah[row * 72 + kk]));
#pragma unroll
                for (int nt = 0; nt < 8; nt++) {
                    int p = nt >> 1, q = (nt & 1) * 2;
                    mma16816(acc[mt][nt], ah, bh[p][q], bh[p][q + 1]);
                }
            }
        }
        if (kt < 3) {
            storeA(buf ^ 1, av);
            asm volatile("cp.async.wait_group 0;");
        }
        __syncthreads();
    }

#pragma unroll
    for (int mt = 0; mt < 2; mt++) {
#pragma unroll
        for (int nt = 0; nt < 8; nt++) {
            int col = wn * 64 + nt * 8 + 2 * (lane & 3);
            int r0 = rb + wmi * 32 + mt * 16 + (lane >> 2);
            float b0 = bias[col], b1 = bias[col + 1];
            float v0 = (acc[mt][nt][0] + b0) * SCALE;
            float v1 = (acc[mt][nt][1] + b1) * SCALE;
            float v2 = (acc[mt][nt][2] + b0) * SCALE;
            float v3 = (acc[mt][nt][3] + b1) * SCALE;
            int h = col >> 5, d = col & 31;
            {
                int b = r0 >> 12, s = (r0 >> 3) & 511, vv = r0 & 7;
                int dst = (((h << 3) + vv) * 4 + b) * (SEG * DQ) + s * DQ + d;
                *(uint32_t*)&g_qh[dst] = pack_f16(v0, v1);
            }
            {
                int r1 = r0 + 8;
                int b = r1 >> 12, s = (r1 >> 3) & 511, vv = r1 & 7;
                int dst = (((h << 3) + vv) * 4 + b) * (SEG * DQ) + s * DQ + d;
                *(uint32_t*)&g_qh[dst] = pack_f16(v2, v3);
            }
        }
    }
}

// ---------------------------------------------------------------------------
// gemm1: fc + bias + residual + fused LN. 64x256 tile, BK=64, 2-stage,
// 2 CTAs/SM. (R15 config, unchanged)
// ---------------------------------------------------------------------------
#define G1_A (64 * 72)
#define G1_W (256 * 72)
#define G1_SMEM ((2 * G1_A + 2 * G1_W) * 2)   // 92160

__global__ __launch_bounds__(256, 2) void gemm1(
    const f16* __restrict__ Ah_g, const f16* __restrict__ Wh_g,
    const float* __restrict__ bias, const float* __restrict__ resid,
    const float* __restrict__ gamma, const float* __restrict__ beta,
    float* __restrict__ Cp)
{
    extern __shared__ char smem_raw[];
    f16* Ahp = (f16*)smem_raw;          // [2][64][72]
    f16* Whp = Ahp + 2 * G1_A;          // [2][256][72]

    const int rb = blockIdx.x * 64;
    const int tid = threadIdx.x, lane = tid & 31, w = tid >> 5;
    const int wmi = w & 1, wn = w >> 1;

    auto issue = [&](int kt, int buf) {
#pragma unroll
        for (int u = 0; u < 10; u++) {
            int idx = tid + u * 256;
            if (idx < 512) {
                int row = idx >> 3, q = (idx & 7) * 8;
                cpasync16(sptr(Ahp + buf * G1_A + row * 72 + q),
                          Ah_g + (size_t)(rb + row) * 256 + kt * 64 + q);
            } else {
                int i2 = idx - 512;
                int row = i2 >> 3, q = (i2 & 7) * 8;
                cpasync16(sptr(Whp + buf * G1_W + row * 72 + q),
                          Wh_g + (size_t)row * 256 + kt * 64 + q);
            }
        }
        asm volatile("cp.async.commit_group;");
    };

    float acc[2][8][4];
#pragma unroll
    for (int i = 0; i < 2; i++)
#pragma unroll
        for (int j = 0; j < 8; j++)
#pragma unroll
            for (int k = 0; k < 4; k++) acc[i][j][k] = 0.f;

    issue(0, 0);
    asm volatile("cp.async.wait_group 0;");
    __syncthreads();

#pragma unroll 1
    for (int kt = 0; kt < 4; kt++) {
        const int buf = kt & 1;
        if (kt < 3) issue(kt + 1, buf ^ 1);
        f16* Ah = Ahp + buf * G1_A;
        f16* Wh = Whp + buf * G1_W;
#pragma unroll
        for (int ks = 0; ks < 4; ks++) {
            uint32_t bh[4][4];
#pragma unroll
            for (int p = 0; p < 4; p++) {
                int row = wn * 64 + p * 16 + ((lane >> 4) << 3) + (lane & 7);
                int kk = ks * 16 + ((lane >> 3) & 1) * 8;
                ldsm4(bh[p][0], bh[p][1], bh[p][2], bh[p][3], sptr(&Wh[row * 72 + kk]));
            }
#pragma unroll
            for (int mt = 0; mt < 2; mt++) {
                int row = wmi * 32 + mt * 16 + (lane & 15);
                int kk = ks * 16 + (lane >> 4) * 8;
                uint32_t ah[4];
                ldsm4(ah[0], ah[1], ah[2], ah[3], sptr(&Ah[row * 72 + kk]));
#pragma unroll
                for (int nt = 0; nt < 8; nt++) {
                    int p = nt >> 1, q = (nt & 1) * 2;
                    mma16816(acc[mt][nt], ah, bh[p][q], bh[p][q + 1]);
                }
            }
        }
        asm volatile("cp.async.wait_group 0;");
        __syncthreads();
    }

    float2* red = (float2*)smem_raw;                  // [64][4]
    float* mus = (float*)(smem_raw + 4096);           // [64]
    float* rss = (float*)(smem_raw + 4096 + 256);     // [64]

#pragma unroll
    for (int mt = 0; mt < 2; mt++) {
        float s0 = 0.f, q0 = 0.f, s1 = 0.f, q1 = 0.f;
        int rl = wmi * 32 + mt * 16 + (lane >> 2);
#pragma unroll
        for (int nt = 0; nt < 8; nt++) {
            int col = wn * 64 + nt * 8 + 2 * (lane & 3);
            float b0 = bias[col], b1 = bias[col + 1];
            float2 rx0 = *(const float2*)&resid[(size_t)(rb + rl) * 256 + col];
            float2 rx1 = *(const float2*)&resid[(size_t)(rb + rl + 8) * 256 + col];
            acc[mt][nt][0] += b0 + rx0.x;
            acc[mt][nt][1] += b1 + rx0.y;
            acc[mt][nt][2] += b0 + rx1.x;
            acc[mt][nt][3] += b1 + rx1.y;
            s0 += acc[mt][nt][0] + acc[mt][nt][1];
            q0 += acc[mt][nt][0] * acc[mt][nt][0] + acc[mt][nt][1] * acc[mt][nt][1];
            s1 += acc[mt][nt][2] + acc[mt][nt][3];
            q1 += acc[mt][nt][2] * acc[mt][nt][2] + acc[mt][nt][3] * acc[mt][nt][3];
        }
#pragma unroll
        for (int o = 1; o <= 2; o <<= 1) {
            s0 += __shfl_xor_sync(0xffffffffu, s0, o);
            q0 += __shfl_xor_sync(0xffffffffu, q0, o);
            s1 += __shfl_xor_sync(0xffffffffu, s1, o);
            q1 += __shfl_xor_sync(0xffffffffu, q1, o);
        }
        if ((lane & 3) == 0) {
            red[rl * 4 + wn] = make_float2(s0, q0);
            red[(rl + 8) * 4 + wn] = make_float2(s1, q1);
        }
    }
    __syncthreads();
    if (tid < 64) {
        float s = 0.f, q = 0.f;
#pragma unroll
        for (int j = 0; j < 4; j++) {
            float2 p = red[tid * 4 + j];
            s += p.x;
            q += p.y;
        }
        float mu = s * (1.f / 256.f);
        float var = q * (1.f / 256.f) - mu * mu;
        mus[tid] = mu;
        rss[tid] = rsqrtf(var + 1e-5f);
    }
    __syncthreads();
#pragma unroll
    for (int nt = 0; nt < 8; nt++) {
        int col = wn * 64 + nt * 8 + 2 * (lane & 3);
        float g0 = gamma[col], g1 = gamma[col + 1];
        float be0 = beta[col], be1 = beta[col + 1];
#pragma unroll
        for (int mt = 0; mt < 2; mt++) {
            int rl = wmi * 32 + mt * 16 + (lane >> 2);
            float mu0 = mus[rl], rs0 = rss[rl];
            float mu1 = mus[rl + 8], rs1 = rss[rl + 8];
            float2 o0 = { (acc[mt][nt][0] - mu0) * rs0 * g0 + be0,
                          (acc[mt][nt][1] - mu0) * rs0 * g1 + be1 };
            float2 o1 = { (acc[mt][nt][2] - mu1) * rs1 * g0 + be0,
                          (acc[mt][nt][3] - mu1) * rs1 * g1 + be1 };
            *(float2*)&Cp[(size_t)(rb + rl) * 256 + col] = o0;
            *(float2*)&Cp[(size_t)(rb + rl + 8) * 256 + col] = o1;
        }
    }
}

// ---------------------------------------------------------------------------
// Attention: 4 CTAs/group (128 rows, 128 thr), occ5, z cvt during staging.
// MMA1 f16-accumulate (2x rate; output regs feed ex2.f16x2 directly).
// MMA2 f32-accumulate.
// ---------------------------------------------------------------------------
struct AttnCtx {
    f16* zh;
    int lane;
    uint32_t qfh[2][2][4];
};

// S in f16: s[mt][nt][2] packed regs
__device__ __forceinline__ void attn_mma1(AttnCtx& c, int ct, uint32_t s[2][2][2]) {
#pragma unroll
    for (int i = 0; i < 2; i++)
#pragma unroll
        for (int j = 0; j < 2; j++) {
            s[i][j][0] = 0u;
            s[i][j][1] = 0u;
        }
    const int t0 = ct * 16;
#pragma unroll
    for (int ks = 0; ks < 2; ks++) {
        int zr = t0 + ((c.lane >> 4) << 3) + (c.lane & 7);
        int zk = ks * 16 + ((c.lane >> 3) & 1) * 8;
        uint32_t zbh[4];
        ldsm4(zbh[0], zbh[1], zbh[2], zbh[3], sptr(&c.zh[zr * 40 + zk]));
#pragma unroll
        for (int mt = 0; mt < 2; mt++)
#pragma unroll
            for (int nt = 0; nt < 2; nt++)
                mma16816_h(s[mt][nt], c.qfh[mt][ks], zbh[nt * 2], zbh[nt * 2 + 1]);
    }
}

__device__ __forceinline__ void attn_softmax(uint32_t s[2][2][2], uint32_t pah[2][4],
                                             float dn[2][2]) {
#pragma unroll
    for (int mt = 0; mt < 2; mt++) {
#pragma unroll
        for (int nt = 0; nt < 2; nt++) {
            pah[mt][nt * 2]     = ex2_f16x2(s[mt][nt][0]);   // rows r   : (p0,p1)
            pah[mt][nt * 2 + 1] = ex2_f16x2(s[mt][nt][1]);   // rows r+8 : (p2,p3)
        }
        __half2 h0 = __hadd2(*(__half2*)&pah[mt][0], *(__half2*)&pah[mt][2]);
        __half2 h1 = __hadd2(*(__half2*)&pah[mt][1], *(__half2*)&pah[mt][3]);
        float2 f0 = __half22float2(h0);
        float2 f1 = __half22float2(h1);
        dn[mt][0] += f0.x + f0.y;
        dn[mt][1] += f1.x + f1.y;
    }
}

__global__ __launch_bounds__(128, 5) void attn_mma(const float* __restrict__ zf) {
    extern __shared__ __align__(16) f16 zsm[];
    AttnCtx c;
    c.zh = zsm;   // [512][40]

    const int g = blockIdx.x >> 2, quarter = blockIdx.x & 3;
    const int tid = threadIdx.x, w = tid >> 5;
    c.lane = tid & 31;
    const int lane = c.lane;
    const int h = g >> 5, v = (g >> 2) & 7, b = g & 3;

    const float* zg = zf + (size_t)g * SEG * DQ;
#pragma unroll
    for (int u = 0; u < 32; u++) {
        int idx = tid + u * 128;
        int row = idx >> 3, j = idx & 7;
        float4 vz = *(const float4*)&zg[row * 32 + j * 4];
        *(uint2*)&c.zh[row * 40 + j * 4] =
            make_uint2(pack_f16(vz.x, vz.y), pack_f16(vz.z, vz.w));
    }

    const f16* qph = g_qh + (size_t)g * SEG * DQ;
    const int m0 = quarter * 128 + w * 32;
#pragma unroll
    for (int mt = 0; mt < 2; mt++)
#pragma unroll
        for (int ks = 0; ks < 2; ks++) {
            int row = m0 + mt * 16 + (lane >> 2);
            int kk = ks * 16 + 2 * (lane & 3);
            c.qfh[mt][ks][0] = *(const uint32_t*)&qph[row * 32 + kk];
            c.qfh[mt][ks][1] = *(const uint32_t*)&qph[(row + 8) * 32 + kk];
            c.qfh[mt][ks][2] = *(const uint32_t*)&qph[row * 32 + kk + 8];
            c.qfh[mt][ks][3] = *(const uint32_t*)&qph[(row + 8) * 32 + kk + 8];
        }

    float o[2][4][4];
#pragma unroll
    for (int i = 0; i < 2; i++)
#pragma unroll
        for (int j = 0; j < 4; j++)
#pragma unroll
            for (int k = 0; k < 4; k++) o[i][j][k] = 0.f;
    float dn[2][2] = {{0.f, 0.f}, {0.f, 0.f}};

    __syncthreads();

    uint32_t s[2][2][2];
    attn_mma1(c, 0, s);

#pragma unroll 1
    for (int ct = 0; ct < 32; ct++) {
        uint32_t zth[2][4];
        const int t0 = ct * 16;
#pragma unroll
        for (int dp = 0; dp < 2; dp++) {
            int zr = t0 + (((lane >> 3) & 1) << 3) + (lane & 7);
            int zc = dp * 16 + (lane >> 4) * 8;
            ldsm4t(zth[dp][0], zth[dp][1], zth[dp][2], zth[dp][3],
                   sptr(&c.zh[zr * 40 + zc]));
        }
        uint32_t pah[2][4];
        attn_softmax(s, pah, dn);
        if (ct < 31) {
            uint32_t s2[2][2][2];
            attn_mma1(c, ct + 1, s2);
#pragma unroll
            for (int i = 0; i < 2; i++)
#pragma unroll
                for (int j = 0; j < 2; j++) {
                    s[i][j][0] = s2[i][j][0];
                    s[i][j][1] = s2[i][j][1];
                }
        }
#pragma unroll
        for (int dp = 0; dp < 2; dp++)
#pragma unroll
            for (int mt = 0; mt < 2; mt++)
#pragma unroll
                for (int nt = 0; nt < 2; nt++)
                    mma16816(o[mt][dp * 2 + nt], pah[mt],
                             zth[dp][nt * 2], zth[dp][nt * 2 + 1]);
    }

    float inv[2][2];
#pragma unroll
    for (int mt = 0; mt < 2; mt++)
#pragma unroll
        for (int rh = 0; rh < 2; rh++) {
            float d = dn[mt][rh];
            d += __shfl_xor_sync(0xffffffffu, d, 1);
            d += __shfl_xor_sync(0xffffffffu, d, 2);
            inv[mt][rh] = __fdividef(1.f, d);
        }

#pragma unroll
    for (int mt = 0; mt < 2; mt++) {
        int s0 = m0 + mt * 16 + (lane >> 2);
        int r0 = ((b * SEG + s0) * 8) + v;
        int r1 = ((b * SEG + s0 + 8) * 8) + v;
#pragma unroll
        for (int n = 0; n < 4; n++) {
            int col = h * 32 + n * 8 + 2 * (lane & 3);
            *(uint32_t*)&g_oh[(size_t)r0 * 256 + col] =
                pack_f16(o[mt][n][0] * inv[mt][0], o[mt][n][1] * inv[mt][0]);
            *(uint32_t*)&g_oh[(size_t)r1 * 256 + col] =
                pack_f16(o[mt][n][2] * inv[mt][1], o[mt][n][3] * inv[mt][1]);
        }
    }
}

// ---------------------------------------------------------------------------

extern "C" void kernel_launch(void* const* d_in, const int* in_sizes, int n_in,
                              void* d_out, int out_size)
{
    const float* x     = (const float*)d_in[0];
    const float* z     = (const float*)d_in[1];
    const float* wq    = (const float*)d_in[2];
    const float* wqb   = (const float*)d_in[3];
    const float* fcw   = (const float*)d_in[4];
    const float* fcb   = (const float*)d_in[5];
    const float* gamma = (const float*)d_in[6];
    const float* beta  = (const float*)d_in[7];
    float* y = (float*)d_out;

    static f16 *oh_p = nullptr, *wqh_p, *fh_p;
    if (!oh_p) {
        cudaGetSymbolAddress((void**)&oh_p, g_oh);
        cudaGetSymbolAddress((void**)&wqh_p, g_wqh);
        cudaGetSymbolAddress((void**)&fh_p, g_fh);
        cudaFuncSetAttribute(gemm0, cudaFuncAttributeMaxDynamicSharedMemorySize, G0_SMEM);
        cudaFuncSetAttribute(gemm1, cudaFuncAttributeMaxDynamicSharedMemorySize, G1_SMEM);
        cudaFuncSetAttribute(attn_mma, cudaFuncAttributeMaxDynamicSharedMemorySize, 512 * 40 * 2);
    }

    prep<<<128, 256>>>(wq, fcw);
    gemm0<<<256, 256, G0_SMEM>>>(x, wqh_p, wqb);
    attn_mma<<<NG * 4, 128, 512 * 40 * 2>>>(z);
    gemm1<<<256, 256, G1_SMEM>>>(oh_p, fh_p, fcb, x, gamma, beta, y);
}

// round 17
// speedup vs baseline: 1.2248x; 1.0367x over previous
#include <cuda_runtime.h>
#include <cuda_fp16.h>
#include <cstdint>

// ---------------------------------------------------------------------------
// bs=4 seg=512 nv=8 h=8 dq=32 din=256; tokens=16384, groups=256
// ALL-FP16 datapath. R17 = R16 + attn chunk-pair pipeline (2 independent
// S/P chains in flight per warp, occ4/128regs).
//  prep  : Wq, fc -> fp16 planes
//  gemm0 : q = (x@WqT + b)*log2e/temp; 64x256 tile, BK=64 (frozen R15)
//  attn  : 4 CTAs/group (128 rows, 128 thr); MMA1 f16-acc, ex2.f16x2,
//          MMA2 f32-acc; chunk-pair pipelined
//  gemm1 : fc + bias + residual + fused LN; 64x256, BK=64 (frozen R15)
// ---------------------------------------------------------------------------

#define NTOK 16384
#define SEG  512
#define DQ   32
#define NG   256
#define SCALE 0.2550353055731662f   // log2(e)/sqrt(32)

typedef __half f16;

__device__ f16 g_qh[NG * SEG * DQ];
__device__ f16 g_oh[NTOK * 256];
__device__ f16 g_wqh[256 * 256];
__device__ f16 g_fh[256 * 256];

// ---------------- helpers ----------------
__device__ __forceinline__ uint32_t sptr(const void* p) {
    return (uint32_t)__cvta_generic_to_shared(p);
}
__device__ __forceinline__ void ldsm4(uint32_t& r0, uint32_t& r1, uint32_t& r2,
                                      uint32_t& r3, uint32_t a) {
    asm volatile("ldmatrix.sync.aligned.m8n8.x4.shared.b16 {%0,%1,%2,%3}, [%4];"
                 : "=r"(r0), "=r"(r1), "=r"(r2), "=r"(r3) : "r"(a));
}
__device__ __forceinline__ void ldsm4t(uint32_t& r0, uint32_t& r1, uint32_t& r2,
                                       uint32_t& r3, uint32_t a) {
    asm volatile("ldmatrix.sync.aligned.m8n8.x4.trans.shared.b16 {%0,%1,%2,%3}, [%4];"
                 : "=r"(r0), "=r"(r1), "=r"(r2), "=r"(r3) : "r"(a));
}
__device__ __forceinline__ void mma16816(float* d, const uint32_t* a,
                                         uint32_t b0, uint32_t b1) {
    asm volatile(
        "mma.sync.aligned.m16n8k16.row.col.f32.f16.f16.f32 "
        "{%0,%1,%2,%3}, {%4,%5,%6,%7}, {%8,%9}, {%0,%1,%2,%3};"
        : "+f"(d[0]), "+f"(d[1]), "+f"(d[2]), "+f"(d[3])
        : "r"(a[0]), "r"(a[1]), "r"(a[2]), "r"(a[3]), "r"(b0), "r"(b1));
}
__device__ __forceinline__ void mma16816_h(uint32_t* d, const uint32_t* a,
                                           uint32_t b0, uint32_t b1) {
    asm volatile(
        "mma.sync.aligned.m16n8k16.row.col.f16.f16.f16.f16 "
        "{%0,%1}, {%2,%3,%4,%5}, {%6,%7}, {%0,%1};"
        : "+r"(d[0]), "+r"(d[1])
        : "r"(a[0]), "r"(a[1]), "r"(a[2]), "r"(a[3]), "r"(b0), "r"(b1));
}
__device__ __forceinline__ uint32_t pack_f16(float x, float y) {
    __half2 h = __floats2half2_rn(x, y);
    return *(uint32_t*)&h;
}
__device__ __forceinline__ uint32_t ex2_f16x2(uint32_t a) {
    uint32_t r;
    asm("ex2.approx.f16x2 %0, %1;" : "=r"(r) : "r"(a));
    return r;
}
__device__ __forceinline__ void cpasync16(uint32_t dst, const void* src) {
    asm volatile("cp.async.ca.shared.global [%0], [%1], 16;" :: "r"(dst), "l"(src));
}

// ---------------- prep: weights fp32 -> fp16 ----------------
__global__ __launch_bounds__(256) void prep(const float* __restrict__ wq,
                                            const float* __restrict__ fcw) {
    int blk = blockIdx.x;
    const float* src = (blk < 64) ? wq : fcw;
    f16* dh = (blk < 64) ? g_wqh : g_fh;
    int i = ((blk < 64) ? blk : blk - 64) * 256 + threadIdx.x;
    float4 v = ((const float4*)src)[i];
    ((uint2*)dh)[i] = make_uint2(pack_f16(v.x, v.y), pack_f16(v.z, v.w));
}

// ---------------------------------------------------------------------------
// gemm0 (frozen R15): 64x256 tile, 256 thr, BK=64, 2-stage, 2 CTAs/SM.
// ---------------------------------------------------------------------------
#define G0_A (64 * 72)
#define G0_W (256 * 72)
#define G0_SMEM ((2 * G0_A + 2 * G0_W) * 2)   // 92160

__global__ __launch_bounds__(256, 2) void gemm0(
    const float* __restrict__ Xf, const f16* __restrict__ Wh_g,
    const float* __restrict__ bias)
{
    extern __shared__ char smem_raw[];
    f16* Ahp = (f16*)smem_raw;          // [2][64][72]
    f16* Whp = Ahp + 2 * G0_A;          // [2][256][72]

    const int rb = blockIdx.x * 64;
    const int tid = threadIdx.x, lane = tid & 31, w = tid >> 5;
    const int wmi = w & 1, wn = w >> 1;

    auto issueW = [&](int kt, int buf) {
#pragma unroll
        for (int u = 0; u < 8; u++) {
            int idx = tid + u * 256;
            int row = idx >> 3, q = (idx & 7) * 8;
            cpasync16(sptr(Whp + buf * G0_W + row * 72 + q),
                      Wh_g + (size_t)row * 256 + kt * 64 + q);
        }
        asm volatile("cp.async.commit_group;");
    };
    auto loadA = [&](int kt, float4* av) {
#pragma unroll
        for (int u = 0; u < 4; u++) {
            int c = tid + u * 256;
            int row = c >> 4, j = c & 15;
            av[u] = *(const float4*)&Xf[(size_t)(rb + row) * 256 + kt * 64 + j * 4];
        }
    };
    auto storeA = [&](int buf, const float4* av) {
#pragma unroll
        for (int u = 0; u < 4; u++) {
            int c = tid + u * 256;
            int row = c >> 4, j = c & 15;
            *(uint2*)&Ahp[buf * G0_A + row * 72 + j * 4] =
                make_uint2(pack_f16(av[u].x, av[u].y), pack_f16(av[u].z, av[u].w));
        }
    };

    float acc[2][8][4];
#pragma unroll
    for (int i = 0; i < 2; i++)
#pragma unroll
        for (int j = 0; j < 8; j++)
#pragma unroll
            for (int k = 0; k < 4; k++) acc[i][j][k] = 0.f;

    {
        issueW(0, 0);
        float4 av[4];
        loadA(0, av);
        storeA(0, av);
        asm volatile("cp.async.wait_group 0;");
    }
    __syncthreads();

#pragma unroll 1
    for (int kt = 0; kt < 4; kt++) {
        const int buf = kt & 1;
        float4 av[4];
        if (kt < 3) {
            issueW(kt + 1, buf ^ 1);
            loadA(kt + 1, av);
        }
        f16* Ah = Ahp + buf * G0_A;
        f16* Wh = Whp + buf * G0_W;
#pragma unroll
        for (int ks = 0; ks < 4; ks++) {
            uint32_t bh[4][4];
#pragma unroll
            for (int p = 0; p < 4; p++) {
                int row = wn * 64 + p * 16 + ((lane >> 4) << 3) + (lane & 7);
                int kk = ks * 16 + ((lane >> 3) & 1) * 8;
                ldsm4(bh[p][0], bh[p][1], bh[p][2], bh[p][3], sptr(&Wh[row * 72 + kk]));
            }
#pragma unroll
            for (int mt = 0; mt < 2; mt++) {
                int row = wmi * 32 + mt * 16 + (lane & 15);
                int kk = ks * 16 + (lane >> 4) * 8;
                uint32_t ah[4];
                ldsm4(ah[0], ah[1], ah[2], ah[3], sptr(&Ah[row * 72 + kk]));
#pragma unroll
                for (int nt = 0; nt < 8; nt++) {
                    int p = nt >> 1, q = (nt & 1) * 2;
                    mma16816(acc[mt][nt], ah, bh[p][q], bh[p][q + 1]);
                }
            }
        }
        if (kt < 3) {
            storeA(buf ^ 1, av);
            asm volatile("cp.async.wait_group 0;");
        }
        __syncthreads();
    }

#pragma unroll
    for (int mt = 0; mt < 2; mt++) {
#pragma unroll
        for (int nt = 0; nt < 8; nt++) {
            int col = wn * 64 + nt * 8 + 2 * (lane & 3);
            int r0 = rb + wmi * 32 + mt * 16 + (lane >> 2);
            float b0 = bias[col], b1 = bias[col + 1];
            float v0 = (acc[mt][nt][0] + b0) * SCALE;
            float v1 = (acc[mt][nt][1] + b1) * SCALE;
            float v2 = (acc[mt][nt][2] + b0) * SCALE;
            float v3 = (acc[mt][nt][3] + b1) * SCALE;
            int h = col >> 5, d = col & 31;
            {
                int b = r0 >> 12, s = (r0 >> 3) & 511, vv = r0 & 7;
                int dst = (((h << 3) + vv) * 4 + b) * (SEG * DQ) + s * DQ + d;
                *(uint32_t*)&g_qh[dst] = pack_f16(v0, v1);
            }
            {
                int r1 = r0 + 8;
                int b = r1 >> 12, s = (r1 >> 3) & 511, vv = r1 & 7;
                int dst = (((h << 3) + vv) * 4 + b) * (SEG * DQ) + s * DQ + d;
                *(uint32_t*)&g_qh[dst] = pack_f16(v2, v3);
            }
        }
    }
}

// ---------------------------------------------------------------------------
// gemm1 (frozen R15): fc + bias + residual + fused LN. 64x256, BK=64.
// ---------------------------------------------------------------------------
#define G1_A (64 * 72)
#define G1_W (256 * 72)
#define G1_SMEM ((2 * G1_A + 2 * G1_W) * 2)   // 92160

__global__ __launch_bounds__(256, 2) void gemm1(
    const f16* __restrict__ Ah_g, const f16* __restrict__ Wh_g,
    const float* __restrict__ bias, const float* __restrict__ resid,
    const float* __restrict__ gamma, const float* __restrict__ beta,
    float* __restrict__ Cp)
{
    extern __shared__ char smem_raw[];
    f16* Ahp = (f16*)smem_raw;          // [2][64][72]
    f16* Whp = Ahp + 2 * G1_A;          // [2][256][72]

    const int rb = blockIdx.x * 64;
    const int tid = threadIdx.x, lane = tid & 31, w = tid >> 5;
    const int wmi = w & 1, wn = w >> 1;

    auto issue = [&](int kt, int buf) {
#pragma unroll
        for (int u = 0; u < 10; u++) {
            int idx = tid + u * 256;
            if (idx < 512) {
                int row = idx >> 3, q = (idx & 7) * 8;
                cpasync16(sptr(Ahp + buf * G1_A + row * 72 + q),
                          Ah_g + (size_t)(rb + row) * 256 + kt * 64 + q);
            } else {
                int i2 = idx - 512;
                int row = i2 >> 3, q = (i2 & 7) * 8;
                cpasync16(sptr(Whp + buf * G1_W + row * 72 + q),
                          Wh_g + (size_t)row * 256 + kt * 64 + q);
            }
        }
        asm volatile("cp.async.commit_group;");
    };

    float acc[2][8][4];
#pragma unroll
    for (int i = 0; i < 2; i++)
#pragma unroll
        for (int j = 0; j < 8; j++)
#pragma unroll
            for (int k = 0; k < 4; k++) acc[i][j][k] = 0.f;

    issue(0, 0);
    asm volatile("cp.async.wait_group 0;");
    __syncthreads();

#pragma unroll 1
    for (int kt = 0; kt < 4; kt++) {
        const int buf = kt & 1;
        if (kt < 3) issue(kt + 1, buf ^ 1);
        f16* Ah = Ahp + buf * G1_A;
        f16* Wh = Whp + buf * G1_W;
#pragma unroll
        for (int ks = 0; ks < 4; ks++) {
            uint32_t bh[4][4];
#pragma unroll
            for (int p = 0; p < 4; p++) {
                int row = wn * 64 + p * 16 + ((lane >> 4) << 3) + (lane & 7);
                int kk = ks * 16 + ((lane >> 3) & 1) * 8;
                ldsm4(bh[p][0], bh[p][1], bh[p][2], bh[p][3], sptr(&Wh[row * 72 + kk]));
            }
#pragma unroll
            for (int mt = 0; mt < 2; mt++) {
                int row = wmi * 32 + mt * 16 + (lane & 15);
                int kk = ks * 16 + (lane >> 4) * 8;
                uint32_t ah[4];
                ldsm4(ah[0], ah[1], ah[2], ah[3], sptr(&Ah[row * 72 + kk]));
#pragma unroll
                for (int nt = 0; nt < 8; nt++) {
                    int p = nt >> 1, q = (nt & 1) * 2;
                    mma16816(acc[mt][nt], ah, bh[p][q], bh[p][q + 1]);
                }
            }
        }
        asm volatile("cp.async.wait_group 0;");
        __syncthreads();
    }

    float2* red = (float2*)smem_raw;                  // [64][4]
    float* mus = (float*)(smem_raw + 4096);           // [64]
    float* rss = (float*)(smem_raw + 4096 + 256);     // [64]

#pragma unroll
    for (int mt = 0; mt < 2; mt++) {
        float s0 = 0.f, q0 = 0.f, s1 = 0.f, q1 = 0.f;
        int rl = wmi * 32 + mt * 16 + (lane >> 2);
#pragma unroll
        for (int nt = 0; nt < 8; nt++) {
            int col = wn * 64 + nt * 8 + 2 * (lane & 3);
            float b0 = bias[col], b1 = bias[col + 1];
            float2 rx0 = *(const float2*)&resid[(size_t)(rb + rl) * 256 + col];
            float2 rx1 = *(const float2*)&resid[(size_t)(rb + rl + 8) * 256 + col];
            acc[mt][nt][0] += b0 + rx0.x;
            acc[mt][nt][1] += b1 + rx0.y;
            acc[mt][nt][2] += b0 + rx1.x;
            acc[mt][nt][3] += b1 + rx1.y;
            s0 += acc[mt][nt][0] + acc[mt][nt][1];
            q0 += acc[mt][nt][0] * acc[mt][nt][0] + acc[mt][nt][1] * acc[mt][nt][1];
            s1 += acc[mt][nt][2] + acc[mt][nt][3];
            q1 += acc[mt][nt][2] * acc[mt][nt][2] + acc[mt][nt][3] * acc[mt][nt][3];
        }
#pragma unroll
        for (int o = 1; o <= 2; o <<= 1) {
            s0 += __shfl_xor_sync(0xffffffffu, s0, o);
            q0 += __shfl_xor_sync(0xffffffffu, q0, o);
            s1 += __shfl_xor_sync(0xffffffffu, s1, o);
            q1 += __shfl_xor_sync(0xffffffffu, q1, o);
        }
        if ((lane & 3) == 0) {
            red[rl * 4 + wn] = make_float2(s0, q0);
            red[(rl + 8) * 4 + wn] = make_float2(s1, q1);
        }
    }
    __syncthreads();
    if (tid < 64) {
        float s = 0.f, q = 0.f;
#pragma unroll
        for (int j = 0; j < 4; j++) {
            float2 p = red[tid * 4 + j];
            s += p.x;
            q += p.y;
        }
        float mu = s * (1.f / 256.f);
        float var = q * (1.f / 256.f) - mu * mu;
        mus[tid] = mu;
        rss[tid] = rsqrtf(var + 1e-5f);
    }
    __syncthreads();
#pragma unroll
    for (int nt = 0; nt < 8; nt++) {
        int col = wn * 64 + nt * 8 + 2 * (lane & 3);
        float g0 = gamma[col], g1 = gamma[col + 1];
        float be0 = beta[col], be1 = beta[col + 1];
#pragma unroll
        for (int mt = 0; mt < 2; mt++) {
            int rl = wmi * 32 + mt * 16 + (lane >> 2);
            float mu0 = mus[rl], rs0 = rss[rl];
            float mu1 = mus[rl + 8], rs1 = rss[rl + 8];
            float2 o0 = { (acc[mt][nt][0] - mu0) * rs0 * g0 + be0,
                          (acc[mt][nt][1] - mu0) * rs0 * g1 + be1 };
            float2 o1 = { (acc[mt][nt][2] - mu1) * rs1 * g0 + be0,
                          (acc[mt][nt][3] - mu1) * rs1 * g1 + be1 };
            *(float2*)&Cp[(size_t)(rb + rl) * 256 + col] = o0;
            *(float2*)&Cp[(size_t)(rb + rl + 8) * 256 + col] = o1;
        }
    }
}

// ---------------------------------------------------------------------------
// Attention: 4 CTAs/group (128 rows, 128 thr, occ4/128regs). z cvt during
// staging. Chunk-pair pipeline: two independent S(f16-acc)/P chains.
// ---------------------------------------------------------------------------
struct AttnCtx {
    f16* zh;
    int lane;
    uint32_t qfh[2][2][4];
};

__device__ __forceinline__ void attn_mma1(AttnCtx& c, int ct, uint32_t s[2][2][2]) {
#pragma unroll
    for (int i = 0; i < 2; i++)
#pragma unroll
        for (int j = 0; j < 2; j++) {
            s[i][j][0] = 0u;
            s[i][j][1] = 0u;
        }
    const int t0 = ct * 16;
#pragma unroll
    for (int ks = 0; ks < 2; ks++) {
        int zr = t0 + ((c.lane >> 4) << 3) + (c.lane & 7);
        int zk = ks * 16 + ((c.lane >> 3) & 1) * 8;
        uint32_t zbh[4];
        ldsm4(zbh[0], zbh[1], zbh[2], zbh[3], sptr(&c.zh[zr * 40 + zk]));
#pragma unroll
        for (int mt = 0; mt < 2; mt++)
#pragma unroll
            for (int nt = 0; nt < 2; nt++)
                mma16816_h(s[mt][nt], c.qfh[mt][ks], zbh[nt * 2], zbh[nt * 2 + 1]);
    }
}

__device__ __forceinline__ void attn_softmax(uint32_t s[2][2][2], uint32_t pah[2][4],
                                             float dn[2][2]) {
#pragma unroll
    for (int mt = 0; mt < 2; mt++) {
#pragma unroll
        for (int nt = 0; nt < 2; nt++) {
            pah[mt][nt * 2]     = ex2_f16x2(s[mt][nt][0]);
            pah[mt][nt * 2 + 1] = ex2_f16x2(s[mt][nt][1]);
        }
        __half2 h0 = __hadd2(*(__half2*)&pah[mt][0], *(__half2*)&pah[mt][2]);
        __half2 h1 = __hadd2(*(__half2*)&pah[mt][1], *(__half2*)&pah[mt][3]);
        float2 f0 = __half22float2(h0);
        float2 f1 = __half22float2(h1);
        dn[mt][0] += f0.x + f0.y;
        dn[mt][1] += f1.x + f1.y;
    }
}

__device__ __forceinline__ void attn_ldz(AttnCtx& c, int ct, uint32_t zth[2][4]) {
    const int t0 = ct * 16;
#pragma unroll
    for (int dp = 0; dp < 2; dp++) {
        int zr = t0 + (((c.lane >> 3) & 1) << 3) + (c.lane & 7);
        int zc = dp * 16 + (c.lane >> 4) * 8;
        ldsm4t(zth[dp][0], zth[dp][1], zth[dp][2], zth[dp][3],
               sptr(&c.zh[zr * 40 + zc]));
    }
}

__device__ __forceinline__ void attn_mma2(uint32_t zth[2][4], uint32_t pah[2][4],
                                          float o[2][4][4]) {
#pragma unroll
    for (int dp = 0; dp < 2; dp++)
#pragma unroll
        for (int mt = 0; mt < 2; mt++)
#pragma unroll
            for (int nt = 0; nt < 2; nt++)
                mma16816(o[mt][dp * 2 + nt], pah[mt],
                         zth[dp][nt * 2], zth[dp][nt * 2 + 1]);
}

__global__ __launch_bounds__(128, 4) void attn_mma(const float* __restrict__ zf) {
    extern __shared__ __align__(16) f16 zsm[];
    AttnCtx c;
    c.zh = zsm;   // [512][40]

    const int g = blockIdx.x >> 2, quarter = blockIdx.x & 3;
    const int tid = threadIdx.x, w = tid >> 5;
    c.lane = tid & 31;
    const int lane = c.lane;
    const int h = g >> 5, v = (g >> 2) & 7, b = g & 3;

    const float* zg = zf + (size_t)g * SEG * DQ;
#pragma unroll
    for (int u = 0; u < 32; u++) {
        int idx = tid + u * 128;
        int row = idx >> 3, j = idx & 7;
        float4 vz = *(const float4*)&zg[row * 32 + j * 4];
        *(uint2*)&c.zh[row * 40 + j * 4] =
            make_uint2(pack_f16(vz.x, vz.y), pack_f16(vz.z, vz.w));
    }

    const f16* qph = g_qh + (size_t)g * SEG * DQ;
    const int m0 = quarter * 128 + w * 32;
#pragma unroll
    for (int mt = 0; mt < 2; mt++)
#pragma unroll
        for (int ks = 0; ks < 2; ks++) {
            int row = m0 + mt * 16 + (lane >> 2);
            int kk = ks * 16 + 2 * (lane & 3);
            c.qfh[mt][ks][0] = *(const uint32_t*)&qph[row * 32 + kk];
            c.qfh[mt][ks][1] = *(const uint32_t*)&qph[(row + 8) * 32 + kk];
            c.qfh[mt][ks][2] = *(const uint32_t*)&qph[row * 32 + kk + 8];
            c.qfh[mt][ks][3] = *(const uint32_t*)&qph[(row + 8) * 32 + kk + 8];
        }

    float o[2][4][4];
#pragma unroll
    for (int i = 0; i < 2; i++)
#pragma unroll
        for (int j = 0; j < 4; j++)
#pragma unroll
            for (int k = 0; k < 4; k++) o[i][j][k] = 0.f;
    float dn[2][2] = {{0.f, 0.f}, {0.f, 0.f}};

    __syncthreads();

    uint32_t s0[2][2][2];
    attn_mma1(c, 0, s0);

#pragma unroll 1
    for (int ct = 0; ct < 32; ct += 2) {
        // two independent chains in flight
        uint32_t zth0[2][4], zth1[2][4];
        attn_ldz(c, ct, zth0);
        uint32_t s1[2][2][2];
        attn_mma1(c, ct + 1, s1);          // chain B: S for ct+1

        uint32_t pah0[2][4];
        attn_softmax(s0, pah0, dn);        // chain A: softmax(ct) overlaps above

        attn_ldz(c, ct + 1, zth1);
        if (ct < 30) attn_mma1(c, ct + 2, s0);  // chain A: next S

        attn_mma2(zth0, pah0, o);          // chain A: AV(ct)

        uint32_t pah1[2][4];
        attn_softmax(s1, pah1, dn);        // chain B: softmax(ct+1)
        attn_mma2(zth1, pah1, o);          // chain B: AV(ct+1)
    }

    float inv[2][2];
#pragma unroll
    for (int mt = 0; mt < 2; mt++)
#pragma unroll
        for (int rh = 0; rh < 2; rh++) {
            float d = dn[mt][rh];
            d += __shfl_xor_sync(0xffffffffu, d, 1);
            d += __shfl_xor_sync(0xffffffffu, d, 2);
            inv[mt][rh] = __fdividef(1.f, d);
        }

#pragma unroll
    for (int mt = 0; mt < 2; mt++) {
        int sr = m0 + mt * 16 + (lane >> 2);
        int r0 = ((b * SEG + sr) * 8) + v;
        int r1 = ((b * SEG + sr + 8) * 8) + v;
#pragma unroll
        for (int n = 0; n < 4; n++) {
            int col = h * 32 + n * 8 + 2 * (lane & 3);
            *(uint32_t*)&g_oh[(size_t)r0 * 256 + col] =
                pack_f16(o[mt][n][0] * inv[mt][0], o[mt][n][1] * inv[mt][0]);
            *(uint32_t*)&g_oh[(size_t)r1 * 256 + col] =
                pack_f16(o[mt][n][2] * inv[mt][1], o[mt][n][3] * inv[mt][1]);
        }
    }
}

// ---------------------------------------------------------------------------

extern "C" void kernel_launch(void* const* d_in, const int* in_sizes, int n_in,
                              void* d_out, int out_size)
{
    const float* x     = (const float*)d_in[0];
    const float* z     = (const float*)d_in[1];
    const float* wq    = (const float*)d_in[2];
    const float* wqb   = (const float*)d_in[3];
    const float* fcw   = (const float*)d_in[4];
    const float* fcb   = (const float*)d_in[5];
    const float* gamma = (const float*)d_in[6];
    const float* beta  = (const float*)d_in[7];
    float* y = (float*)d_out;

    static f16 *oh_p = nullptr, *wqh_p, *fh_p;
    if (!oh_p) {
        cudaGetSymbolAddress((void**)&oh_p, g_oh);
        cudaGetSymbolAddress((void**)&wqh_p, g_wqh);
        cudaGetSymbolAddress((void**)&fh_p, g_fh);
        cudaFuncSetAttribute(gemm0, cudaFuncAttributeMaxDynamicSharedMemorySize, G0_SMEM);
        cudaFuncSetAttribute(gemm1, cudaFuncAttributeMaxDynamicSharedMemorySize, G1_SMEM);
        cudaFuncSetAttribute(attn_mma, cudaFuncAttributeMaxDynamicSharedMemorySize, 512 * 40 * 2);
    }

    prep<<<128, 256>>>(wq, fcw);
    gemm0<<<256, 256, G0_SMEM>>>(x, wqh_p, wqb);
    attn_mma<<<NG * 4, 128, 512 * 40 * 2>>>(z);
    gemm1<<<256, 256, G1_SMEM>>>(oh_p, fh_p, fcb, x, gamma, beta, y);
}